// round 4
// baseline (speedup 1.0000x reference)
#include <cuda_runtime.h>
#include <math.h>

typedef unsigned long long ull;

// ---------------- packed f32x2 helpers (Blackwell) ----------------
__device__ __forceinline__ ull f2_fma(ull a, ull b, ull c) {
    ull d; asm("fma.rn.f32x2 %0, %1, %2, %3;" : "=l"(d) : "l"(a), "l"(b), "l"(c)); return d;
}
__device__ __forceinline__ ull f2_add(ull a, ull b) {
    ull d; asm("add.rn.f32x2 %0, %1, %2;" : "=l"(d) : "l"(a), "l"(b)); return d;
}
__device__ __forceinline__ ull f2_mul(ull a, ull b) {
    ull d; asm("mul.rn.f32x2 %0, %1, %2;" : "=l"(d) : "l"(a), "l"(b)); return d;
}
__device__ __forceinline__ ull f2_pack(float lo, float hi) {
    ull d; asm("mov.b64 %0, {%1, %2};" : "=l"(d) : "f"(lo), "f"(hi)); return d;
}
__device__ __forceinline__ void f2_unpack(float& lo, float& hi, ull v) {
    asm("mov.b64 {%0, %1}, %2;" : "=f"(lo), "=f"(hi) : "l"(v));
}

// ---------------- scratch (static device globals; no allocation) ----------------
__device__ float g_q  [(size_t)4 * 4096 * 256];   // [b][n][oc]
__device__ float g_kv [(size_t)4 * 1024 * 512];   // [b][m][oc]
__device__ float g_vpe[(size_t)4 * 1024 * 256];   // [b][m][c]
__device__ float g_pre[(size_t)4 * 4096 * 256];   // [b][n][c]

// =================================================================================
// conv1x1, input planar [C][Nsp], output n-major [Nsp][O]
// =================================================================================
__global__ __launch_bounds__(256) void k_conv1x1_nmajor(
    const float* __restrict__ X, const float* __restrict__ W,
    const float* __restrict__ scale, const float* __restrict__ bias,
    float* __restrict__ out, int C, int Nsp, int O)
{
    __shared__ float As[16][68];   // [k][n]
    __shared__ float Ws[16][68];   // [k][o]
    const int b  = blockIdx.z;
    const int n0 = blockIdx.y * 64;
    const int o0 = blockIdx.x * 64;
    const int tid = threadIdx.x;
    const int tx = tid & 15, ty = tid >> 4;

    const float* Xb = X + (size_t)b * C * Nsp;
    ull acc2[4][2];   // [n][o-pair]
    #pragma unroll
    for (int i = 0; i < 4; i++) { acc2[i][0] = 0ull; acc2[i][1] = 0ull; }

    for (int c0 = 0; c0 < C; c0 += 16) {
        {
            int n  = tid & 63;
            int kb = tid >> 6;
            #pragma unroll
            for (int kk = 0; kk < 4; kk++) {
                int k = kb + 4 * kk;
                As[k][n] = Xb[(size_t)(c0 + k) * Nsp + n0 + n];
            }
        }
        {
            int k  = tid & 15;
            int ob = tid >> 4;
            #pragma unroll
            for (int oo = 0; oo < 4; oo++) {
                int o = ob + 16 * oo;
                Ws[k][o] = W[(size_t)(o0 + o) * C + c0 + k];
            }
        }
        __syncthreads();
        #pragma unroll
        for (int k = 0; k < 16; k++) {
            float4 a = *(const float4*)&As[k][ty * 4];
            ulonglong2 w2 = *(const ulonglong2*)&Ws[k][tx * 4];
            ull a0 = f2_pack(a.x, a.x), a1 = f2_pack(a.y, a.y);
            ull a2 = f2_pack(a.z, a.z), a3 = f2_pack(a.w, a.w);
            acc2[0][0] = f2_fma(a0, w2.x, acc2[0][0]);
            acc2[0][1] = f2_fma(a0, w2.y, acc2[0][1]);
            acc2[1][0] = f2_fma(a1, w2.x, acc2[1][0]);
            acc2[1][1] = f2_fma(a1, w2.y, acc2[1][1]);
            acc2[2][0] = f2_fma(a2, w2.x, acc2[2][0]);
            acc2[2][1] = f2_fma(a2, w2.y, acc2[2][1]);
            acc2[3][0] = f2_fma(a3, w2.x, acc2[3][0]);
            acc2[3][1] = f2_fma(a3, w2.y, acc2[3][1]);
        }
        __syncthreads();
    }

    const int o = o0 + tx * 4;
    float4 sc = *(const float4*)&scale[o];
    float4 bi = *(const float4*)&bias[o];
    #pragma unroll
    for (int jn = 0; jn < 4; jn++) {
        int n = n0 + ty * 4 + jn;
        float a0, a1, a2, a3;
        f2_unpack(a0, a1, acc2[jn][0]);
        f2_unpack(a2, a3, acc2[jn][1]);
        float4 r;
        r.x = a0 * sc.x + bi.x;
        r.y = a1 * sc.y + bi.y;
        r.z = a2 * sc.z + bi.z;
        r.w = a3 * sc.w + bi.w;
        *(float4*)&out[((size_t)b * Nsp + n) * O + o] = r;
    }
}

// =================================================================================
// conv1x1, input row-major [Nsp][C], output planar [O][Nsp]  (final projection)
// =================================================================================
__global__ __launch_bounds__(256) void k_conv1x1_planar(
    const float* __restrict__ A, const float* __restrict__ W,
    const float* __restrict__ scale, const float* __restrict__ bias,
    float* __restrict__ out, int C, int Nsp, int O)
{
    __shared__ float As[16][68];   // [k][n]
    __shared__ float Ws[16][68];   // [k][o]
    const int b  = blockIdx.z;
    const int n0 = blockIdx.y * 64;
    const int o0 = blockIdx.x * 64;
    const int tid = threadIdx.x;
    const int tx = tid & 15, ty = tid >> 4;

    const float* Ab = A + (size_t)b * Nsp * C;
    ull acc2[4][2];   // [o][n-pair]
    #pragma unroll
    for (int i = 0; i < 4; i++) { acc2[i][0] = 0ull; acc2[i][1] = 0ull; }

    for (int c0 = 0; c0 < C; c0 += 16) {
        {
            int k  = tid & 15;
            int nb = tid >> 4;
            #pragma unroll
            for (int nn = 0; nn < 4; nn++) {
                int n = nb + 16 * nn;
                As[k][n] = Ab[(size_t)(n0 + n) * C + c0 + k];
            }
        }
        {
            int k  = tid & 15;
            int ob = tid >> 4;
            #pragma unroll
            for (int oo = 0; oo < 4; oo++) {
                int o = ob + 16 * oo;
                Ws[k][o] = W[(size_t)(o0 + o) * C + c0 + k];
            }
        }
        __syncthreads();
        #pragma unroll
        for (int k = 0; k < 16; k++) {
            ulonglong2 a2 = *(const ulonglong2*)&As[k][tx * 4];  // n pairs
            float4 w = *(const float4*)&Ws[k][ty * 4];           // o scalars
            ull w0 = f2_pack(w.x, w.x), w1 = f2_pack(w.y, w.y);
            ull w2 = f2_pack(w.z, w.z), w3 = f2_pack(w.w, w.w);
            acc2[0][0] = f2_fma(w0, a2.x, acc2[0][0]);
            acc2[0][1] = f2_fma(w0, a2.y, acc2[0][1]);
            acc2[1][0] = f2_fma(w1, a2.x, acc2[1][0]);
            acc2[1][1] = f2_fma(w1, a2.y, acc2[1][1]);
            acc2[2][0] = f2_fma(w2, a2.x, acc2[2][0]);
            acc2[2][1] = f2_fma(w2, a2.y, acc2[2][1]);
            acc2[3][0] = f2_fma(w3, a2.x, acc2[3][0]);
            acc2[3][1] = f2_fma(w3, a2.y, acc2[3][1]);
        }
        __syncthreads();
    }

    #pragma unroll
    for (int jo = 0; jo < 4; jo++) {
        int o = o0 + ty * 4 + jo;
        float sc = scale[o], bi = bias[o];
        float n0v, n1v, n2v, n3v;
        f2_unpack(n0v, n1v, acc2[jo][0]);
        f2_unpack(n2v, n3v, acc2[jo][1]);
        float4 r;
        r.x = n0v * sc + bi;
        r.y = n1v * sc + bi;
        r.z = n2v * sc + bi;
        r.w = n3v * sc + bi;
        *(float4*)&out[((size_t)b * O + o) * Nsp + n0 + tx * 4] = r;
    }
}

// =================================================================================
// attention with packed f32x2 math.
// per block = 128 q rows of one (b,h). One thread = one q row.
// smem kv rows read as ulonglong2 -> two packed f32x2 operands per LDS.128.
// =================================================================================
__global__ __launch_bounds__(128) void k_attn(
    const float* __restrict__ q, const float* __restrict__ kv, float* __restrict__ pre)
{
    __shared__ float kvs[64][64];
    const int bh = blockIdx.y;
    const int b = bh >> 3, h = bh & 7;
    const int n = blockIdx.x * 128 + threadIdx.x;

    // q row as 16 packed pairs
    const ulonglong2* qrow = (const ulonglong2*)(q + ((size_t)b * 4096 + n) * 256 + h * 32);
    ull qr2[16];
    #pragma unroll
    for (int i = 0; i < 8; i++) {
        ulonglong2 t = qrow[i];
        qr2[2 * i] = t.x; qr2[2 * i + 1] = t.y;
    }

    ull acc2[16];
    #pragma unroll
    for (int i = 0; i < 16; i++) acc2[i] = 0ull;
    float l = 0.0f;

    const float* kvb = kv + (size_t)b * 1024 * 512 + h * 64;
    const float SCL = 0.17677669529663687f;   // 1/sqrt(32)

    for (int mc = 0; mc < 1024; mc += 64) {
        __syncthreads();
        #pragma unroll
        for (int ii = 0; ii < 8; ii++) {
            int idx = threadIdx.x + 128 * ii;        // 0..1023
            int r = idx >> 4;
            int j = (idx & 15) << 2;
            *(float4*)&kvs[r][j] = *(const float4*)&kvb[(size_t)(mc + r) * 512 + j];
        }
        __syncthreads();

        #pragma unroll 2
        for (int m = 0; m < 64; m++) {
            const ulonglong2* row = (const ulonglong2*)&kvs[m][0];
            // ---- QK: 16 packed FMAs into 4 packed partials ----
            ull s0 = 0ull, s1 = 0ull, s2 = 0ull, s3 = 0ull;
            #pragma unroll
            for (int i = 0; i < 4; i++) {
                ulonglong2 ka = row[2 * i];
                ulonglong2 kb2 = row[2 * i + 1];
                s0 = f2_fma(qr2[4 * i + 0], ka.x,  s0);
                s1 = f2_fma(qr2[4 * i + 1], ka.y,  s1);
                s2 = f2_fma(qr2[4 * i + 2], kb2.x, s2);
                s3 = f2_fma(qr2[4 * i + 3], kb2.y, s3);
            }
            ull sr = f2_add(f2_add(s0, s1), f2_add(s2, s3));
            float slo, shi;
            f2_unpack(slo, shi, sr);
            float p = __expf((slo + shi) * SCL);
            l += p;
            ull p2 = f2_pack(p, p);
            // ---- AV: 16 packed FMAs ----
            #pragma unroll
            for (int i = 0; i < 4; i++) {
                ulonglong2 va = row[8 + 2 * i];
                ulonglong2 vb2 = row[8 + 2 * i + 1];
                acc2[4 * i + 0] = f2_fma(p2, va.x,  acc2[4 * i + 0]);
                acc2[4 * i + 1] = f2_fma(p2, va.y,  acc2[4 * i + 1]);
                acc2[4 * i + 2] = f2_fma(p2, vb2.x, acc2[4 * i + 2]);
                acc2[4 * i + 3] = f2_fma(p2, vb2.y, acc2[4 * i + 3]);
            }
        }
    }

    float inv = 1.0f / l;
    ull inv2 = f2_pack(inv, inv);
    ulonglong2* orow = (ulonglong2*)(pre + ((size_t)b * 4096 + n) * 256 + h * 32);
    #pragma unroll
    for (int i = 0; i < 8; i++) {
        ulonglong2 r;
        r.x = f2_mul(acc2[2 * i + 0], inv2);
        r.y = f2_mul(acc2[2 * i + 1], inv2);
        orow[i] = r;
    }
}

// =================================================================================
// depthwise 7x7 conv (pad 3) on v + scale/bias -> g_vpe[b][m][c]
// =================================================================================
__global__ __launch_bounds__(256) void k_dwconv(
    const float* __restrict__ kv, const float* __restrict__ Wpe,
    const float* __restrict__ pe_scale, const float* __restrict__ pe_bias,
    float* __restrict__ vpe)
{
    __shared__ float plane[32][32];
    __shared__ float wsm[49];
    const int c = blockIdx.x;
    const int b = blockIdx.y;
    const int tid = threadIdx.x;

    const int col = (c >> 5) * 64 + 32 + (c & 31);   // v channel inside kv row
    #pragma unroll
    for (int i = 0; i < 4; i++) {
        int m = tid + 256 * i;
        plane[m >> 5][m & 31] = kv[((size_t)b * 1024 + m) * 512 + col];
    }
    if (tid < 49) wsm[tid] = Wpe[c * 49 + tid];
    __syncthreads();

    const float sc = pe_scale[c], bi = pe_bias[c];
    #pragma unroll
    for (int i = 0; i < 4; i++) {
        int m = tid + 256 * i;
        int y = m >> 5, x = m & 31;
        float s = 0.0f;
        #pragma unroll
        for (int ky = 0; ky < 7; ky++) {
            int iy = y + ky - 3;
            if ((unsigned)iy < 32u) {
                #pragma unroll
                for (int kx = 0; kx < 7; kx++) {
                    int ix = x + kx - 3;
                    if ((unsigned)ix < 32u) s += plane[iy][ix] * wsm[ky * 7 + kx];
                }
            }
        }
        vpe[((size_t)b * 1024 + m) * 256 + c] = s * sc + bi;
    }
}

// =================================================================================
// bilinear x2 upsample + add into pre
// =================================================================================
__global__ __launch_bounds__(256) void k_upsample_add(
    const float* __restrict__ vpe, float* __restrict__ pre)
{
    const int y = blockIdx.x;
    const int b = blockIdx.y;
    const int c = threadIdx.x;

    float ys = y * 0.5f - 0.25f;
    int y0 = (int)floorf(ys);
    float wy = ys - (float)y0;
    int y0c = max(y0, 0), y1c = min(y0 + 1, 31);

    const float* vb = vpe + (size_t)b * 1024 * 256;

    for (int x = 0; x < 64; x++) {
        float xs = x * 0.5f - 0.25f;
        int x0 = (int)floorf(xs);
        float wx = xs - (float)x0;
        int x0c = max(x0, 0), x1c = min(x0 + 1, 31);

        float v00 = vb[(y0c * 32 + x0c) * 256 + c];
        float v01 = vb[(y0c * 32 + x1c) * 256 + c];
        float v10 = vb[(y1c * 32 + x0c) * 256 + c];
        float v11 = vb[(y1c * 32 + x1c) * 256 + c];
        float val = (1.f - wy) * ((1.f - wx) * v00 + wx * v01)
                  +        wy  * ((1.f - wx) * v10 + wx * v11);

        size_t o = ((size_t)b * 4096 + y * 64 + x) * 256 + c;
        pre[o] += val;
    }
}

// =================================================================================
// launch
// =================================================================================
extern "C" void kernel_launch(void* const* d_in, const int* in_sizes, int n_in,
                              void* d_out, int out_size)
{
    (void)in_sizes; (void)n_in; (void)out_size;
    const float* x          = (const float*)d_in[0];
    const float* upper_feat = (const float*)d_in[1];
    const float* Wq         = (const float*)d_in[2];
    const float* q_scale    = (const float*)d_in[3];
    const float* q_bias     = (const float*)d_in[4];
    const float* Wkv        = (const float*)d_in[5];
    const float* kv_scale   = (const float*)d_in[6];
    const float* kv_bias    = (const float*)d_in[7];
    const float* Wpe        = (const float*)d_in[8];
    const float* pe_scale   = (const float*)d_in[9];
    const float* pe_bias    = (const float*)d_in[10];
    const float* Wproj      = (const float*)d_in[11];
    const float* proj_scale = (const float*)d_in[12];
    const float* proj_bias  = (const float*)d_in[13];
    float* out = (float*)d_out;

    float *pq, *pkv, *pvpe, *ppre;
    cudaGetSymbolAddress((void**)&pq,   g_q);
    cudaGetSymbolAddress((void**)&pkv,  g_kv);
    cudaGetSymbolAddress((void**)&pvpe, g_vpe);
    cudaGetSymbolAddress((void**)&ppre, g_pre);

    k_conv1x1_nmajor<<<dim3(4, 64, 4), 256>>>(x, Wq, q_scale, q_bias, pq, 256, 4096, 256);
    k_conv1x1_nmajor<<<dim3(8, 16, 4), 256>>>(upper_feat, Wkv, kv_scale, kv_bias, pkv, 256, 1024, 512);
    k_attn<<<dim3(32, 32), 128>>>(pq, pkv, ppre);
    k_dwconv<<<dim3(256, 4), 256>>>(pkv, Wpe, pe_scale, pe_bias, pvpe);
    k_upsample_add<<<dim3(64, 4), 256>>>(pvpe, ppre);
    k_conv1x1_planar<<<dim3(4, 64, 4), 256>>>(ppre, Wproj, proj_scale, proj_bias, out, 256, 4096, 256);
}

// round 5
// speedup vs baseline: 1.0002x; 1.0002x over previous
#include <cuda_runtime.h>
#include <math.h>

typedef unsigned long long ull;

// ---------------- packed f32x2 helpers (Blackwell) ----------------
__device__ __forceinline__ ull f2_fma(ull a, ull b, ull c) {
    ull d; asm("fma.rn.f32x2 %0, %1, %2, %3;" : "=l"(d) : "l"(a), "l"(b), "l"(c)); return d;
}
__device__ __forceinline__ ull f2_add(ull a, ull b) {
    ull d; asm("add.rn.f32x2 %0, %1, %2;" : "=l"(d) : "l"(a), "l"(b)); return d;
}
__device__ __forceinline__ ull f2_mul(ull a, ull b) {
    ull d; asm("mul.rn.f32x2 %0, %1, %2;" : "=l"(d) : "l"(a), "l"(b)); return d;
}
__device__ __forceinline__ ull f2_pack(float lo, float hi) {
    ull d; asm("mov.b64 %0, {%1, %2};" : "=l"(d) : "f"(lo), "f"(hi)); return d;
}
__device__ __forceinline__ void f2_unpack(float& lo, float& hi, ull v) {
    asm("mov.b64 {%0, %1}, %2;" : "=f"(lo), "=f"(hi) : "l"(v));
}

// ---------------- scratch (static device globals; no allocation) ----------------
__device__ float g_q  [(size_t)4 * 4096 * 256];   // [b][n][oc]
__device__ float g_kv [(size_t)4 * 1024 * 512];   // [b][m][oc]
__device__ float g_vpe[(size_t)4 * 1024 * 256];   // [b][m][c]
__device__ float g_pre[(size_t)4 * 4096 * 256];   // [b][n][c]

// =================================================================================
// conv1x1, input planar [C][Nsp], output n-major [Nsp][O]
// =================================================================================
__global__ __launch_bounds__(256) void k_conv1x1_nmajor(
    const float* __restrict__ X, const float* __restrict__ W,
    const float* __restrict__ scale, const float* __restrict__ bias,
    float* __restrict__ out, int C, int Nsp, int O)
{
    __shared__ float As[16][68];   // [k][n]
    __shared__ float Ws[16][68];   // [k][o]
    const int b  = blockIdx.z;
    const int n0 = blockIdx.y * 64;
    const int o0 = blockIdx.x * 64;
    const int tid = threadIdx.x;
    const int tx = tid & 15, ty = tid >> 4;

    const float* Xb = X + (size_t)b * C * Nsp;
    ull acc2[4][2];   // [n][o-pair]
    #pragma unroll
    for (int i = 0; i < 4; i++) { acc2[i][0] = 0ull; acc2[i][1] = 0ull; }

    for (int c0 = 0; c0 < C; c0 += 16) {
        {
            int n  = tid & 63;
            int kb = tid >> 6;
            #pragma unroll
            for (int kk = 0; kk < 4; kk++) {
                int k = kb + 4 * kk;
                As[k][n] = Xb[(size_t)(c0 + k) * Nsp + n0 + n];
            }
        }
        {
            int k  = tid & 15;
            int ob = tid >> 4;
            #pragma unroll
            for (int oo = 0; oo < 4; oo++) {
                int o = ob + 16 * oo;
                Ws[k][o] = W[(size_t)(o0 + o) * C + c0 + k];
            }
        }
        __syncthreads();
        #pragma unroll
        for (int k = 0; k < 16; k++) {
            float4 a = *(const float4*)&As[k][ty * 4];
            ulonglong2 w2 = *(const ulonglong2*)&Ws[k][tx * 4];
            ull a0 = f2_pack(a.x, a.x), a1 = f2_pack(a.y, a.y);
            ull a2 = f2_pack(a.z, a.z), a3 = f2_pack(a.w, a.w);
            acc2[0][0] = f2_fma(a0, w2.x, acc2[0][0]);
            acc2[0][1] = f2_fma(a0, w2.y, acc2[0][1]);
            acc2[1][0] = f2_fma(a1, w2.x, acc2[1][0]);
            acc2[1][1] = f2_fma(a1, w2.y, acc2[1][1]);
            acc2[2][0] = f2_fma(a2, w2.x, acc2[2][0]);
            acc2[2][1] = f2_fma(a2, w2.y, acc2[2][1]);
            acc2[3][0] = f2_fma(a3, w2.x, acc2[3][0]);
            acc2[3][1] = f2_fma(a3, w2.y, acc2[3][1]);
        }
        __syncthreads();
    }

    const int o = o0 + tx * 4;
    float4 sc = *(const float4*)&scale[o];
    float4 bi = *(const float4*)&bias[o];
    #pragma unroll
    for (int jn = 0; jn < 4; jn++) {
        int n = n0 + ty * 4 + jn;
        float a0, a1, a2, a3;
        f2_unpack(a0, a1, acc2[jn][0]);
        f2_unpack(a2, a3, acc2[jn][1]);
        float4 r;
        r.x = a0 * sc.x + bi.x;
        r.y = a1 * sc.y + bi.y;
        r.z = a2 * sc.z + bi.z;
        r.w = a3 * sc.w + bi.w;
        *(float4*)&out[((size_t)b * Nsp + n) * O + o] = r;
    }
}

// =================================================================================
// conv1x1, input row-major [Nsp][C], output planar [O][Nsp]  (final projection)
// =================================================================================
__global__ __launch_bounds__(256) void k_conv1x1_planar(
    const float* __restrict__ A, const float* __restrict__ W,
    const float* __restrict__ scale, const float* __restrict__ bias,
    float* __restrict__ out, int C, int Nsp, int O)
{
    __shared__ float As[16][68];   // [k][n]
    __shared__ float Ws[16][68];   // [k][o]
    const int b  = blockIdx.z;
    const int n0 = blockIdx.y * 64;
    const int o0 = blockIdx.x * 64;
    const int tid = threadIdx.x;
    const int tx = tid & 15, ty = tid >> 4;

    const float* Ab = A + (size_t)b * Nsp * C;
    ull acc2[4][2];   // [o][n-pair]
    #pragma unroll
    for (int i = 0; i < 4; i++) { acc2[i][0] = 0ull; acc2[i][1] = 0ull; }

    for (int c0 = 0; c0 < C; c0 += 16) {
        {
            int k  = tid & 15;
            int nb = tid >> 4;
            #pragma unroll
            for (int nn = 0; nn < 4; nn++) {
                int n = nb + 16 * nn;
                As[k][n] = Ab[(size_t)(n0 + n) * C + c0 + k];
            }
        }
        {
            int k  = tid & 15;
            int ob = tid >> 4;
            #pragma unroll
            for (int oo = 0; oo < 4; oo++) {
                int o = ob + 16 * oo;
                Ws[k][o] = W[(size_t)(o0 + o) * C + c0 + k];
            }
        }
        __syncthreads();
        #pragma unroll
        for (int k = 0; k < 16; k++) {
            ulonglong2 a2 = *(const ulonglong2*)&As[k][tx * 4];  // n pairs
            float4 w = *(const float4*)&Ws[k][ty * 4];           // o scalars
            ull w0 = f2_pack(w.x, w.x), w1 = f2_pack(w.y, w.y);
            ull w2 = f2_pack(w.z, w.z), w3 = f2_pack(w.w, w.w);
            acc2[0][0] = f2_fma(w0, a2.x, acc2[0][0]);
            acc2[0][1] = f2_fma(w0, a2.y, acc2[0][1]);
            acc2[1][0] = f2_fma(w1, a2.x, acc2[1][0]);
            acc2[1][1] = f2_fma(w1, a2.y, acc2[1][1]);
            acc2[2][0] = f2_fma(w2, a2.x, acc2[2][0]);
            acc2[2][1] = f2_fma(w2, a2.y, acc2[2][1]);
            acc2[3][0] = f2_fma(w3, a2.x, acc2[3][0]);
            acc2[3][1] = f2_fma(w3, a2.y, acc2[3][1]);
        }
        __syncthreads();
    }

    #pragma unroll
    for (int jo = 0; jo < 4; jo++) {
        int o = o0 + ty * 4 + jo;
        float sc = scale[o], bi = bias[o];
        float n0v, n1v, n2v, n3v;
        f2_unpack(n0v, n1v, acc2[jo][0]);
        f2_unpack(n2v, n3v, acc2[jo][1]);
        float4 r;
        r.x = n0v * sc + bi;
        r.y = n1v * sc + bi;
        r.z = n2v * sc + bi;
        r.w = n3v * sc + bi;
        *(float4*)&out[((size_t)b * O + o) * Nsp + n0 + tx * 4] = r;
    }
}

// =================================================================================
// attention with packed f32x2 math.
// per block = 128 q rows of one (b,h). One thread = one q row.
// smem kv rows read as ulonglong2 -> two packed f32x2 operands per LDS.128.
// =================================================================================
__global__ __launch_bounds__(128) void k_attn(
    const float* __restrict__ q, const float* __restrict__ kv, float* __restrict__ pre)
{
    __shared__ float kvs[64][64];
    const int bh = blockIdx.y;
    const int b = bh >> 3, h = bh & 7;
    const int n = blockIdx.x * 128 + threadIdx.x;

    // q row as 16 packed pairs
    const ulonglong2* qrow = (const ulonglong2*)(q + ((size_t)b * 4096 + n) * 256 + h * 32);
    ull qr2[16];
    #pragma unroll
    for (int i = 0; i < 8; i++) {
        ulonglong2 t = qrow[i];
        qr2[2 * i] = t.x; qr2[2 * i + 1] = t.y;
    }

    ull acc2[16];
    #pragma unroll
    for (int i = 0; i < 16; i++) acc2[i] = 0ull;
    float l = 0.0f;

    const float* kvb = kv + (size_t)b * 1024 * 512 + h * 64;
    const float SCL = 0.17677669529663687f;   // 1/sqrt(32)

    for (int mc = 0; mc < 1024; mc += 64) {
        __syncthreads();
        #pragma unroll
        for (int ii = 0; ii < 8; ii++) {
            int idx = threadIdx.x + 128 * ii;        // 0..1023
            int r = idx >> 4;
            int j = (idx & 15) << 2;
            *(float4*)&kvs[r][j] = *(const float4*)&kvb[(size_t)(mc + r) * 512 + j];
        }
        __syncthreads();

        #pragma unroll 2
        for (int m = 0; m < 64; m++) {
            const ulonglong2* row = (const ulonglong2*)&kvs[m][0];
            // ---- QK: 16 packed FMAs into 4 packed partials ----
            ull s0 = 0ull, s1 = 0ull, s2 = 0ull, s3 = 0ull;
            #pragma unroll
            for (int i = 0; i < 4; i++) {
                ulonglong2 ka = row[2 * i];
                ulonglong2 kb2 = row[2 * i + 1];
                s0 = f2_fma(qr2[4 * i + 0], ka.x,  s0);
                s1 = f2_fma(qr2[4 * i + 1], ka.y,  s1);
                s2 = f2_fma(qr2[4 * i + 2], kb2.x, s2);
                s3 = f2_fma(qr2[4 * i + 3], kb2.y, s3);
            }
            ull sr = f2_add(f2_add(s0, s1), f2_add(s2, s3));
            float slo, shi;
            f2_unpack(slo, shi, sr);
            float p = __expf((slo + shi) * SCL);
            l += p;
            ull p2 = f2_pack(p, p);
            // ---- AV: 16 packed FMAs ----
            #pragma unroll
            for (int i = 0; i < 4; i++) {
                ulonglong2 va = row[8 + 2 * i];
                ulonglong2 vb2 = row[8 + 2 * i + 1];
                acc2[4 * i + 0] = f2_fma(p2, va.x,  acc2[4 * i + 0]);
                acc2[4 * i + 1] = f2_fma(p2, va.y,  acc2[4 * i + 1]);
                acc2[4 * i + 2] = f2_fma(p2, vb2.x, acc2[4 * i + 2]);
                acc2[4 * i + 3] = f2_fma(p2, vb2.y, acc2[4 * i + 3]);
            }
        }
    }

    float inv = 1.0f / l;
    ull inv2 = f2_pack(inv, inv);
    ulonglong2* orow = (ulonglong2*)(pre + ((size_t)b * 4096 + n) * 256 + h * 32);
    #pragma unroll
    for (int i = 0; i < 8; i++) {
        ulonglong2 r;
        r.x = f2_mul(acc2[2 * i + 0], inv2);
        r.y = f2_mul(acc2[2 * i + 1], inv2);
        orow[i] = r;
    }
}

// =================================================================================
// depthwise 7x7 conv (pad 3) on v + scale/bias -> g_vpe[b][m][c]
// =================================================================================
__global__ __launch_bounds__(256) void k_dwconv(
    const float* __restrict__ kv, const float* __restrict__ Wpe,
    const float* __restrict__ pe_scale, const float* __restrict__ pe_bias,
    float* __restrict__ vpe)
{
    __shared__ float plane[32][32];
    __shared__ float wsm[49];
    const int c = blockIdx.x;
    const int b = blockIdx.y;
    const int tid = threadIdx.x;

    const int col = (c >> 5) * 64 + 32 + (c & 31);   // v channel inside kv row
    #pragma unroll
    for (int i = 0; i < 4; i++) {
        int m = tid + 256 * i;
        plane[m >> 5][m & 31] = kv[((size_t)b * 1024 + m) * 512 + col];
    }
    if (tid < 49) wsm[tid] = Wpe[c * 49 + tid];
    __syncthreads();

    const float sc = pe_scale[c], bi = pe_bias[c];
    #pragma unroll
    for (int i = 0; i < 4; i++) {
        int m = tid + 256 * i;
        int y = m >> 5, x = m & 31;
        float s = 0.0f;
        #pragma unroll
        for (int ky = 0; ky < 7; ky++) {
            int iy = y + ky - 3;
            if ((unsigned)iy < 32u) {
                #pragma unroll
                for (int kx = 0; kx < 7; kx++) {
                    int ix = x + kx - 3;
                    if ((unsigned)ix < 32u) s += plane[iy][ix] * wsm[ky * 7 + kx];
                }
            }
        }
        vpe[((size_t)b * 1024 + m) * 256 + c] = s * sc + bi;
    }
}

// =================================================================================
// bilinear x2 upsample + add into pre
// =================================================================================
__global__ __launch_bounds__(256) void k_upsample_add(
    const float* __restrict__ vpe, float* __restrict__ pre)
{
    const int y = blockIdx.x;
    const int b = blockIdx.y;
    const int c = threadIdx.x;

    float ys = y * 0.5f - 0.25f;
    int y0 = (int)floorf(ys);
    float wy = ys - (float)y0;
    int y0c = max(y0, 0), y1c = min(y0 + 1, 31);

    const float* vb = vpe + (size_t)b * 1024 * 256;

    for (int x = 0; x < 64; x++) {
        float xs = x * 0.5f - 0.25f;
        int x0 = (int)floorf(xs);
        float wx = xs - (float)x0;
        int x0c = max(x0, 0), x1c = min(x0 + 1, 31);

        float v00 = vb[(y0c * 32 + x0c) * 256 + c];
        float v01 = vb[(y0c * 32 + x1c) * 256 + c];
        float v10 = vb[(y1c * 32 + x0c) * 256 + c];
        float v11 = vb[(y1c * 32 + x1c) * 256 + c];
        float val = (1.f - wy) * ((1.f - wx) * v00 + wx * v01)
                  +        wy  * ((1.f - wx) * v10 + wx * v11);

        size_t o = ((size_t)b * 4096 + y * 64 + x) * 256 + c;
        pre[o] += val;
    }
}

// =================================================================================
// launch
// =================================================================================
extern "C" void kernel_launch(void* const* d_in, const int* in_sizes, int n_in,
                              void* d_out, int out_size)
{
    (void)in_sizes; (void)n_in; (void)out_size;
    const float* x          = (const float*)d_in[0];
    const float* upper_feat = (const float*)d_in[1];
    const float* Wq         = (const float*)d_in[2];
    const float* q_scale    = (const float*)d_in[3];
    const float* q_bias     = (const float*)d_in[4];
    const float* Wkv        = (const float*)d_in[5];
    const float* kv_scale   = (const float*)d_in[6];
    const float* kv_bias    = (const float*)d_in[7];
    const float* Wpe        = (const float*)d_in[8];
    const float* pe_scale   = (const float*)d_in[9];
    const float* pe_bias    = (const float*)d_in[10];
    const float* Wproj      = (const float*)d_in[11];
    const float* proj_scale = (const float*)d_in[12];
    const float* proj_bias  = (const float*)d_in[13];
    float* out = (float*)d_out;

    float *pq, *pkv, *pvpe, *ppre;
    cudaGetSymbolAddress((void**)&pq,   g_q);
    cudaGetSymbolAddress((void**)&pkv,  g_kv);
    cudaGetSymbolAddress((void**)&pvpe, g_vpe);
    cudaGetSymbolAddress((void**)&ppre, g_pre);

    k_conv1x1_nmajor<<<dim3(4, 64, 4), 256>>>(x, Wq, q_scale, q_bias, pq, 256, 4096, 256);
    k_conv1x1_nmajor<<<dim3(8, 16, 4), 256>>>(upper_feat, Wkv, kv_scale, kv_bias, pkv, 256, 1024, 512);
    k_attn<<<dim3(32, 32), 128>>>(pq, pkv, ppre);
    k_dwconv<<<dim3(256, 4), 256>>>(pkv, Wpe, pe_scale, pe_bias, pvpe);
    k_upsample_add<<<dim3(64, 4), 256>>>(pvpe, ppre);
    k_conv1x1_planar<<<dim3(4, 64, 4), 256>>>(ppre, Wproj, proj_scale, proj_bias, out, 256, 4096, 256);
}

// round 6
// speedup vs baseline: 1.9073x; 1.9069x over previous
#include <cuda_runtime.h>
#include <math.h>
#include <stdint.h>

// ---------------- scratch (static device globals; no allocation) ----------------
__device__ float g_q  [(size_t)4 * 4096 * 256];   // [b][n][oc]
__device__ float g_kv [(size_t)4 * 1024 * 512];   // [b][m][oc]
__device__ float g_vpe[(size_t)4 * 1024 * 256];   // [b][m][c]
__device__ float g_pre[(size_t)4 * 4096 * 256];   // [b][n][c]

// ---------------- tf32 helpers ----------------
__device__ __forceinline__ uint32_t f2tf(float f) {
    uint32_t r; asm("cvt.rna.tf32.f32 %0, %1;" : "=r"(r) : "f"(f)); return r;
}
__device__ __forceinline__ void mma_tf32(float c[4], const uint32_t a[4],
                                         uint32_t b0, uint32_t b1) {
    asm("mma.sync.aligned.m16n8k8.row.col.f32.tf32.tf32.f32 "
        "{%0,%1,%2,%3}, {%4,%5,%6,%7}, {%8,%9}, {%0,%1,%2,%3};"
        : "+f"(c[0]), "+f"(c[1]), "+f"(c[2]), "+f"(c[3])
        : "r"(a[0]), "r"(a[1]), "r"(a[2]), "r"(a[3]), "r"(b0), "r"(b1));
}

// =================================================================================
// conv1x1, input planar [C][Nsp], output n-major [Nsp][O]   (scalar FFMA, R2 proven)
// =================================================================================
__global__ __launch_bounds__(256) void k_conv1x1_nmajor(
    const float* __restrict__ X, const float* __restrict__ W,
    const float* __restrict__ scale, const float* __restrict__ bias,
    float* __restrict__ out, int C, int Nsp, int O)
{
    __shared__ float As[16][68];
    __shared__ float Ws[16][68];
    const int b  = blockIdx.z;
    const int n0 = blockIdx.y * 64;
    const int o0 = blockIdx.x * 64;
    const int tid = threadIdx.x;
    const int tx = tid & 15, ty = tid >> 4;

    const float* Xb = X + (size_t)b * C * Nsp;
    float acc[4][4] = {};

    for (int c0 = 0; c0 < C; c0 += 16) {
        {
            int n  = tid & 63;
            int kb = tid >> 6;
            #pragma unroll
            for (int kk = 0; kk < 4; kk++) {
                int k = kb + 4 * kk;
                As[k][n] = Xb[(size_t)(c0 + k) * Nsp + n0 + n];
            }
        }
        {
            int k  = tid & 15;
            int ob = tid >> 4;
            #pragma unroll
            for (int oo = 0; oo < 4; oo++) {
                int o = ob + 16 * oo;
                Ws[k][o] = W[(size_t)(o0 + o) * C + c0 + k];
            }
        }
        __syncthreads();
        #pragma unroll
        for (int k = 0; k < 16; k++) {
            float4 a = *(const float4*)&As[k][ty * 4];
            float4 w = *(const float4*)&Ws[k][tx * 4];
            float av[4] = {a.x, a.y, a.z, a.w};
            float wv[4] = {w.x, w.y, w.z, w.w};
            #pragma unroll
            for (int i = 0; i < 4; i++)
                #pragma unroll
                for (int j = 0; j < 4; j++)
                    acc[i][j] += av[i] * wv[j];
        }
        __syncthreads();
    }

    const int o = o0 + tx * 4;
    float4 sc = *(const float4*)&scale[o];
    float4 bi = *(const float4*)&bias[o];
    #pragma unroll
    for (int jn = 0; jn < 4; jn++) {
        int n = n0 + ty * 4 + jn;
        float4 r;
        r.x = acc[jn][0] * sc.x + bi.x;
        r.y = acc[jn][1] * sc.y + bi.y;
        r.z = acc[jn][2] * sc.z + bi.z;
        r.w = acc[jn][3] * sc.w + bi.w;
        *(float4*)&out[((size_t)b * Nsp + n) * O + o] = r;
    }
}

// =================================================================================
// conv1x1, input row-major [Nsp][C], output planar [O][Nsp]  (final projection)
// =================================================================================
__global__ __launch_bounds__(256) void k_conv1x1_planar(
    const float* __restrict__ A, const float* __restrict__ W,
    const float* __restrict__ scale, const float* __restrict__ bias,
    float* __restrict__ out, int C, int Nsp, int O)
{
    __shared__ float As[16][68];
    __shared__ float Ws[16][68];
    const int b  = blockIdx.z;
    const int n0 = blockIdx.y * 64;
    const int o0 = blockIdx.x * 64;
    const int tid = threadIdx.x;
    const int tx = tid & 15, ty = tid >> 4;

    const float* Ab = A + (size_t)b * Nsp * C;
    float acc[4][4] = {};

    for (int c0 = 0; c0 < C; c0 += 16) {
        {
            int k  = tid & 15;
            int nb = tid >> 4;
            #pragma unroll
            for (int nn = 0; nn < 4; nn++) {
                int n = nb + 16 * nn;
                As[k][n] = Ab[(size_t)(n0 + n) * C + c0 + k];
            }
        }
        {
            int k  = tid & 15;
            int ob = tid >> 4;
            #pragma unroll
            for (int oo = 0; oo < 4; oo++) {
                int o = ob + 16 * oo;
                Ws[k][o] = W[(size_t)(o0 + o) * C + c0 + k];
            }
        }
        __syncthreads();
        #pragma unroll
        for (int k = 0; k < 16; k++) {
            float4 a = *(const float4*)&As[k][tx * 4];
            float4 w = *(const float4*)&Ws[k][ty * 4];
            float av[4] = {a.x, a.y, a.z, a.w};
            float wv[4] = {w.x, w.y, w.z, w.w};
            #pragma unroll
            for (int i = 0; i < 4; i++)
                #pragma unroll
                for (int j = 0; j < 4; j++)
                    acc[i][j] += wv[i] * av[j];
        }
        __syncthreads();
    }

    #pragma unroll
    for (int jo = 0; jo < 4; jo++) {
        int o = o0 + ty * 4 + jo;
        float sc = scale[o], bi = bias[o];
        float4 r;
        r.x = acc[jo][0] * sc + bi;
        r.y = acc[jo][1] * sc + bi;
        r.z = acc[jo][2] * sc + bi;
        r.w = acc[jo][3] * sc + bi;
        *(float4*)&out[((size_t)b * O + o) * Nsp + n0 + tx * 4] = r;
    }
}

// =================================================================================
// attention via tf32 mma.sync (m16n8k8). Block = 64 q rows (4 warps x m16) of one
// (b,h); loops 16 chunks of 64 kv. No-max softmax (scores bounded).
// kvs stride 68 -> K B-frag reads conflict-free. P round-trips smem (stride 72)
// to reshape C-frag -> A-frag.
// =================================================================================
#define KV_STRIDE 68
#define P_STRIDE  72

__global__ __launch_bounds__(128) void k_attn_mma(
    const float* __restrict__ q, const float* __restrict__ kv, float* __restrict__ pre)
{
    __shared__ __align__(16) uint32_t kvs[64 * KV_STRIDE];      // tf32 kv chunk
    __shared__ __align__(16) uint32_t Pbuf[4 * 16 * P_STRIDE];  // per-warp P (tf32)

    const int bh = blockIdx.y;
    const int b = bh >> 3, h = bh & 7;
    const int warp = threadIdx.x >> 5;
    const int lane = threadIdx.x & 31;
    const int gid = lane >> 2, tig = lane & 3;
    const int n0 = blockIdx.x * 64;

    // ---- stage Q tile [64][32] (coalesced) into Pbuf region, build A-frags ----
    {
        float* stage = (float*)Pbuf;   // [64][33]
        #pragma unroll
        for (int i = 0; i < 4; i++) {
            int idx = threadIdx.x + 128 * i;      // 0..511
            int r = idx >> 3, v4 = (idx & 7) * 4;
            float4 t = *(const float4*)&q[((size_t)b * 4096 + n0 + r) * 256 + h * 32 + v4];
            stage[r * 33 + v4 + 0] = t.x;
            stage[r * 33 + v4 + 1] = t.y;
            stage[r * 33 + v4 + 2] = t.z;
            stage[r * 33 + v4 + 3] = t.w;
        }
    }
    __syncthreads();

    uint32_t qA[4][4];   // [ks][frag]
    {
        const float* stage = (const float*)Pbuf;
        int r0 = warp * 16 + gid;
        #pragma unroll
        for (int ks = 0; ks < 4; ks++) {
            int c = ks * 8 + tig;
            qA[ks][0] = f2tf(stage[r0 * 33 + c]);
            qA[ks][1] = f2tf(stage[(r0 + 8) * 33 + c]);
            qA[ks][2] = f2tf(stage[r0 * 33 + c + 4]);
            qA[ks][3] = f2tf(stage[(r0 + 8) * 33 + c + 4]);
        }
    }

    float O[4][4];
    #pragma unroll
    for (int i = 0; i < 4; i++)
        #pragma unroll
        for (int j = 0; j < 4; j++) O[i][j] = 0.0f;
    float l_lo = 0.0f, l_hi = 0.0f;

    const float* kvb = kv + (size_t)b * 1024 * 512 + h * 64;
    const float SCL = 0.17677669529663687f;   // 1/sqrt(32)
    uint32_t* Pw = Pbuf + warp * 16 * P_STRIDE;

    for (int mc = 0; mc < 1024; mc += 64) {
        __syncthreads();
        // load kv chunk -> smem, converting to tf32
        #pragma unroll
        for (int ii = 0; ii < 8; ii++) {
            int idx = threadIdx.x + 128 * ii;     // 0..1023
            int r = idx >> 4;
            int jc = (idx & 15) * 4;
            float4 t = *(const float4*)&kvb[(size_t)(mc + r) * 512 + jc];
            uint4 u;
            u.x = f2tf(t.x); u.y = f2tf(t.y); u.z = f2tf(t.z); u.w = f2tf(t.w);
            *(uint4*)&kvs[r * KV_STRIDE + jc] = u;
        }
        __syncthreads();

        // ---- QK: S[16 q][64 kv] per warp ----
        float S[8][4];
        #pragma unroll
        for (int nt = 0; nt < 8; nt++) {
            S[nt][0] = S[nt][1] = S[nt][2] = S[nt][3] = 0.0f;
            #pragma unroll
            for (int ks = 0; ks < 4; ks++) {
                const uint32_t* krow = &kvs[(nt * 8 + gid) * KV_STRIDE + ks * 8 + tig];
                mma_tf32(S[nt], qA[ks], krow[0], krow[4]);
            }
        }

        // ---- exp, row-sum partials, store P (tf32) ----
        #pragma unroll
        for (int nt = 0; nt < 8; nt++) {
            float p0 = __expf(S[nt][0] * SCL);
            float p1 = __expf(S[nt][1] * SCL);
            float p2 = __expf(S[nt][2] * SCL);
            float p3 = __expf(S[nt][3] * SCL);
            l_lo += p0 + p1;
            l_hi += p2 + p3;
            int c = nt * 8 + 2 * tig;
            Pw[gid * P_STRIDE + c]           = f2tf(p0);
            Pw[gid * P_STRIDE + c + 1]       = f2tf(p1);
            Pw[(gid + 8) * P_STRIDE + c]     = f2tf(p2);
            Pw[(gid + 8) * P_STRIDE + c + 1] = f2tf(p3);
        }
        __syncwarp();

        // ---- AV: O += P[16x64] * V[64x32] ----
        #pragma unroll
        for (int ks = 0; ks < 8; ks++) {
            uint32_t pA[4];
            int c = ks * 8 + tig;
            pA[0] = Pw[gid * P_STRIDE + c];
            pA[1] = Pw[(gid + 8) * P_STRIDE + c];
            pA[2] = Pw[gid * P_STRIDE + c + 4];
            pA[3] = Pw[(gid + 8) * P_STRIDE + c + 4];
            #pragma unroll
            for (int nt = 0; nt < 4; nt++) {
                uint32_t b0 = kvs[(ks * 8 + tig) * KV_STRIDE + 32 + nt * 8 + gid];
                uint32_t b1 = kvs[(ks * 8 + tig + 4) * KV_STRIDE + 32 + nt * 8 + gid];
                mma_tf32(O[nt], pA, b0, b1);
            }
        }
        __syncwarp();
    }

    // ---- reduce l across the tig quad, normalize, write ----
    l_lo += __shfl_xor_sync(0xFFFFFFFF, l_lo, 1);
    l_lo += __shfl_xor_sync(0xFFFFFFFF, l_lo, 2);
    l_hi += __shfl_xor_sync(0xFFFFFFFF, l_hi, 1);
    l_hi += __shfl_xor_sync(0xFFFFFFFF, l_hi, 2);
    float inv_lo = 1.0f / l_lo;
    float inv_hi = 1.0f / l_hi;

    const int rlo = n0 + warp * 16 + gid;
    const int rhi = rlo + 8;
    #pragma unroll
    for (int nt = 0; nt < 4; nt++) {
        int c = h * 32 + nt * 8 + 2 * tig;
        float2 lo = make_float2(O[nt][0] * inv_lo, O[nt][1] * inv_lo);
        float2 hi = make_float2(O[nt][2] * inv_hi, O[nt][3] * inv_hi);
        *(float2*)&pre[((size_t)b * 4096 + rlo) * 256 + c] = lo;
        *(float2*)&pre[((size_t)b * 4096 + rhi) * 256 + c] = hi;
    }
}

// =================================================================================
// depthwise 7x7 conv (pad 3) on v + scale/bias -> g_vpe[b][m][c]
// =================================================================================
__global__ __launch_bounds__(256) void k_dwconv(
    const float* __restrict__ kv, const float* __restrict__ Wpe,
    const float* __restrict__ pe_scale, const float* __restrict__ pe_bias,
    float* __restrict__ vpe)
{
    __shared__ float plane[32][32];
    __shared__ float wsm[49];
    const int c = blockIdx.x;
    const int b = blockIdx.y;
    const int tid = threadIdx.x;

    const int col = (c >> 5) * 64 + 32 + (c & 31);
    #pragma unroll
    for (int i = 0; i < 4; i++) {
        int m = tid + 256 * i;
        plane[m >> 5][m & 31] = kv[((size_t)b * 1024 + m) * 512 + col];
    }
    if (tid < 49) wsm[tid] = Wpe[c * 49 + tid];
    __syncthreads();

    const float sc = pe_scale[c], bi = pe_bias[c];
    #pragma unroll
    for (int i = 0; i < 4; i++) {
        int m = tid + 256 * i;
        int y = m >> 5, x = m & 31;
        float s = 0.0f;
        #pragma unroll
        for (int ky = 0; ky < 7; ky++) {
            int iy = y + ky - 3;
            if ((unsigned)iy < 32u) {
                #pragma unroll
                for (int kx = 0; kx < 7; kx++) {
                    int ix = x + kx - 3;
                    if ((unsigned)ix < 32u) s += plane[iy][ix] * wsm[ky * 7 + kx];
                }
            }
        }
        vpe[((size_t)b * 1024 + m) * 256 + c] = s * sc + bi;
    }
}

// =================================================================================
// bilinear x2 upsample + add into pre
// =================================================================================
__global__ __launch_bounds__(256) void k_upsample_add(
    const float* __restrict__ vpe, float* __restrict__ pre)
{
    const int y = blockIdx.x;
    const int b = blockIdx.y;
    const int c = threadIdx.x;

    float ys = y * 0.5f - 0.25f;
    int y0 = (int)floorf(ys);
    float wy = ys - (float)y0;
    int y0c = max(y0, 0), y1c = min(y0 + 1, 31);

    const float* vb = vpe + (size_t)b * 1024 * 256;

    for (int x = 0; x < 64; x++) {
        float xs = x * 0.5f - 0.25f;
        int x0 = (int)floorf(xs);
        float wx = xs - (float)x0;
        int x0c = max(x0, 0), x1c = min(x0 + 1, 31);

        float v00 = vb[(y0c * 32 + x0c) * 256 + c];
        float v01 = vb[(y0c * 32 + x1c) * 256 + c];
        float v10 = vb[(y1c * 32 + x0c) * 256 + c];
        float v11 = vb[(y1c * 32 + x1c) * 256 + c];
        float val = (1.f - wy) * ((1.f - wx) * v00 + wx * v01)
                  +        wy  * ((1.f - wx) * v10 + wx * v11);

        size_t o = ((size_t)b * 4096 + y * 64 + x) * 256 + c;
        pre[o] += val;
    }
}

// =================================================================================
// launch
// =================================================================================
extern "C" void kernel_launch(void* const* d_in, const int* in_sizes, int n_in,
                              void* d_out, int out_size)
{
    (void)in_sizes; (void)n_in; (void)out_size;
    const float* x          = (const float*)d_in[0];
    const float* upper_feat = (const float*)d_in[1];
    const float* Wq         = (const float*)d_in[2];
    const float* q_scale    = (const float*)d_in[3];
    const float* q_bias     = (const float*)d_in[4];
    const float* Wkv        = (const float*)d_in[5];
    const float* kv_scale   = (const float*)d_in[6];
    const float* kv_bias    = (const float*)d_in[7];
    const float* Wpe        = (const float*)d_in[8];
    const float* pe_scale   = (const float*)d_in[9];
    const float* pe_bias    = (const float*)d_in[10];
    const float* Wproj      = (const float*)d_in[11];
    const float* proj_scale = (const float*)d_in[12];
    const float* proj_bias  = (const float*)d_in[13];
    float* out = (float*)d_out;

    float *pq, *pkv, *pvpe, *ppre;
    cudaGetSymbolAddress((void**)&pq,   g_q);
    cudaGetSymbolAddress((void**)&pkv,  g_kv);
    cudaGetSymbolAddress((void**)&pvpe, g_vpe);
    cudaGetSymbolAddress((void**)&ppre, g_pre);

    k_conv1x1_nmajor<<<dim3(4, 64, 4), 256>>>(x, Wq, q_scale, q_bias, pq, 256, 4096, 256);
    k_conv1x1_nmajor<<<dim3(8, 16, 4), 256>>>(upper_feat, Wkv, kv_scale, kv_bias, pkv, 256, 1024, 512);
    k_attn_mma<<<dim3(64, 32), 128>>>(pq, pkv, ppre);
    k_dwconv<<<dim3(256, 4), 256>>>(pkv, Wpe, pe_scale, pe_bias, pvpe);
    k_upsample_add<<<dim3(64, 4), 256>>>(pvpe, ppre);
    k_conv1x1_planar<<<dim3(4, 64, 4), 256>>>(ppre, Wproj, proj_scale, proj_bias, out, 256, 4096, 256);
}

// round 7
// speedup vs baseline: 2.5329x; 1.3280x over previous
#include <cuda_runtime.h>
#include <math.h>
#include <stdint.h>

// ---------------- scratch (static device globals; no allocation) ----------------
__device__ float g_q  [(size_t)4 * 4096 * 256];   // [b][n][oc]
__device__ float g_kv [(size_t)4 * 1024 * 512];   // [b][m][oc]
__device__ float g_vt [(size_t)4 * 256 * 1024];   // [b][c][m]  planar copy of v
__device__ float g_vpe[(size_t)4 * 1024 * 256];   // [b][m][c]
__device__ float g_pre[(size_t)4 * 4096 * 256];   // [b][n][c]

// ---------------- tf32 helpers ----------------
__device__ __forceinline__ uint32_t f2tf(float f) {
    uint32_t r; asm("cvt.rna.tf32.f32 %0, %1;" : "=r"(r) : "f"(f)); return r;
}
__device__ __forceinline__ void mma_tf32(float c[4], const uint32_t a[4],
                                         uint32_t b0, uint32_t b1) {
    asm("mma.sync.aligned.m16n8k8.row.col.f32.tf32.tf32.f32 "
        "{%0,%1,%2,%3}, {%4,%5,%6,%7}, {%8,%9}, {%0,%1,%2,%3};"
        : "+f"(c[0]), "+f"(c[1]), "+f"(c[2]), "+f"(c[3])
        : "r"(a[0]), "r"(a[1]), "r"(a[2]), "r"(a[3]), "r"(b0), "r"(b1));
}

// =================================================================================
// tf32 conv1x1, input planar [C][Nsp], output n-major [Nsp][O]
// tile 128n x 64o, K chunks of 32. 8 warps: warp w -> n rows [16w,16w+16).
// As[k][m] stride 136 (frag LDS conflict-free), Ws[o][k] stride 36.
// Optional vt: planar scatter of the v half-channels (kv conv only).
// =================================================================================
__global__ __launch_bounds__(256) void k_conv_tf32_nmajor(
    const float* __restrict__ X, const float* __restrict__ W,
    const float* __restrict__ scale, const float* __restrict__ bias,
    float* __restrict__ out, float* __restrict__ vt, int C, int Nsp, int O)
{
    __shared__ __align__(16) uint32_t As[32 * 136];
    __shared__ __align__(16) uint32_t Ws[64 * 36];
    const int b  = blockIdx.z;
    const int n0 = blockIdx.y * 128;
    const int o0 = blockIdx.x * 64;
    const int tid = threadIdx.x;
    const int warp = tid >> 5, lane = tid & 31;
    const int gid = lane >> 2, tig = lane & 3;
    const int wm = warp * 16;

    const float* Xb = X + (size_t)b * C * Nsp;
    float Cacc[8][4];
    #pragma unroll
    for (int i = 0; i < 8; i++)
        #pragma unroll
        for (int j = 0; j < 4; j++) Cacc[i][j] = 0.0f;

    for (int c0 = 0; c0 < C; c0 += 32) {
        __syncthreads();
        // A: [32 k][128 m] from planar X (coalesced along n), tf32 convert
        #pragma unroll
        for (int i = 0; i < 4; i++) {
            int idx = tid + 256 * i;          // 0..1023
            int k = idx >> 5;
            int mq = (idx & 31) * 4;
            float4 t = *(const float4*)&Xb[(size_t)(c0 + k) * Nsp + n0 + mq];
            uint4 u; u.x = f2tf(t.x); u.y = f2tf(t.y); u.z = f2tf(t.z); u.w = f2tf(t.w);
            *(uint4*)&As[k * 136 + mq] = u;
        }
        // B: [64 o][32 k] from W row-major
        #pragma unroll
        for (int i = 0; i < 2; i++) {
            int idx = tid + 256 * i;          // 0..511
            int o = idx >> 3;
            int kq = (idx & 7) * 4;
            float4 t = *(const float4*)&W[(size_t)(o0 + o) * C + c0 + kq];
            uint4 u; u.x = f2tf(t.x); u.y = f2tf(t.y); u.z = f2tf(t.z); u.w = f2tf(t.w);
            *(uint4*)&Ws[o * 36 + kq] = u;
        }
        __syncthreads();
        #pragma unroll
        for (int ks = 0; ks < 4; ks++) {
            int kk = ks * 8 + tig;
            uint32_t aF[4];
            aF[0] = As[kk * 136 + wm + gid];
            aF[1] = As[kk * 136 + wm + gid + 8];
            aF[2] = As[(kk + 4) * 136 + wm + gid];
            aF[3] = As[(kk + 4) * 136 + wm + gid + 8];
            #pragma unroll
            for (int nt = 0; nt < 8; nt++) {
                uint32_t b0 = Ws[(nt * 8 + gid) * 36 + kk];
                uint32_t b1 = Ws[(nt * 8 + gid) * 36 + kk + 4];
                mma_tf32(Cacc[nt], aF, b0, b1);
            }
        }
    }

    const int nlo = n0 + wm + gid, nhi = nlo + 8;
    #pragma unroll
    for (int nt = 0; nt < 8; nt++) {
        int o = o0 + nt * 8 + 2 * tig;
        float2 sc = *(const float2*)&scale[o];
        float2 bi = *(const float2*)&bias[o];
        float2 lo, hi;
        lo.x = Cacc[nt][0] * sc.x + bi.x;
        lo.y = Cacc[nt][1] * sc.y + bi.y;
        hi.x = Cacc[nt][2] * sc.x + bi.x;
        hi.y = Cacc[nt][3] * sc.y + bi.y;
        *(float2*)&out[((size_t)b * Nsp + nlo) * O + o] = lo;
        *(float2*)&out[((size_t)b * Nsp + nhi) * O + o] = hi;
        if (vt != nullptr && (o & 32)) {
            int vc = (o >> 6) * 32 + (o & 31);
            vt[((size_t)b * 256 + vc)     * Nsp + nlo] = lo.x;
            vt[((size_t)b * 256 + vc + 1) * Nsp + nlo] = lo.y;
            vt[((size_t)b * 256 + vc)     * Nsp + nhi] = hi.x;
            vt[((size_t)b * 256 + vc + 1) * Nsp + nhi] = hi.y;
        }
    }
}

// =================================================================================
// tf32 conv1x1 projection: input row-major [Nsp][C], output planar [O][Nsp]
// M-dim = o (128 tile), N-dim = n (64 tile) -> coalesced planar writes.
// A = W[o][c] (direct), B = Ain[n][c] (direct), both row-major [row][k].
// =================================================================================
__global__ __launch_bounds__(256) void k_conv_tf32_proj(
    const float* __restrict__ Ain, const float* __restrict__ W,
    const float* __restrict__ scale, const float* __restrict__ bias,
    float* __restrict__ out, int C, int Nsp, int O)
{
    __shared__ __align__(16) uint32_t Wa[128 * 36];
    __shared__ __align__(16) uint32_t Ab[64 * 36];
    const int b  = blockIdx.z;
    const int o0 = blockIdx.x * 128;
    const int n0 = blockIdx.y * 64;
    const int tid = threadIdx.x;
    const int warp = tid >> 5, lane = tid & 31;
    const int gid = lane >> 2, tig = lane & 3;
    const int wm = warp * 16;

    const float* Ainb = Ain + (size_t)b * Nsp * C;
    float Cacc[8][4];
    #pragma unroll
    for (int i = 0; i < 8; i++)
        #pragma unroll
        for (int j = 0; j < 4; j++) Cacc[i][j] = 0.0f;

    for (int c0 = 0; c0 < C; c0 += 32) {
        __syncthreads();
        // A: [128 o][32 k] from W
        #pragma unroll
        for (int i = 0; i < 4; i++) {
            int idx = tid + 256 * i;          // 0..1023
            int o = idx >> 3;
            int kq = (idx & 7) * 4;
            float4 t = *(const float4*)&W[(size_t)(o0 + o) * C + c0 + kq];
            uint4 u; u.x = f2tf(t.x); u.y = f2tf(t.y); u.z = f2tf(t.z); u.w = f2tf(t.w);
            *(uint4*)&Wa[o * 36 + kq] = u;
        }
        // B: [64 n][32 k] from Ain row-major
        #pragma unroll
        for (int i = 0; i < 2; i++) {
            int idx = tid + 256 * i;          // 0..511
            int n = idx >> 3;
            int kq = (idx & 7) * 4;
            float4 t = *(const float4*)&Ainb[(size_t)(n0 + n) * C + c0 + kq];
            uint4 u; u.x = f2tf(t.x); u.y = f2tf(t.y); u.z = f2tf(t.z); u.w = f2tf(t.w);
            *(uint4*)&Ab[n * 36 + kq] = u;
        }
        __syncthreads();
        #pragma unroll
        for (int ks = 0; ks < 4; ks++) {
            int kk = ks * 8 + tig;
            uint32_t aF[4];
            aF[0] = Wa[(wm + gid) * 36 + kk];
            aF[1] = Wa[(wm + gid + 8) * 36 + kk];
            aF[2] = Wa[(wm + gid) * 36 + kk + 4];
            aF[3] = Wa[(wm + gid + 8) * 36 + kk + 4];
            #pragma unroll
            for (int nt = 0; nt < 8; nt++) {
                uint32_t b0 = Ab[(nt * 8 + gid) * 36 + kk];
                uint32_t b1 = Ab[(nt * 8 + gid) * 36 + kk + 4];
                mma_tf32(Cacc[nt], aF, b0, b1);
            }
        }
    }

    const int olo = o0 + wm + gid, ohi = olo + 8;
    const float sclo = scale[olo], bilo = bias[olo];
    const float schi = scale[ohi], bihi = bias[ohi];
    #pragma unroll
    for (int nt = 0; nt < 8; nt++) {
        int n = n0 + nt * 8 + 2 * tig;
        float2 lo, hi;
        lo.x = Cacc[nt][0] * sclo + bilo;
        lo.y = Cacc[nt][1] * sclo + bilo;
        hi.x = Cacc[nt][2] * schi + bihi;
        hi.y = Cacc[nt][3] * schi + bihi;
        *(float2*)&out[((size_t)b * O + olo) * Nsp + n] = lo;
        *(float2*)&out[((size_t)b * O + ohi) * Nsp + n] = hi;
    }
}

// =================================================================================
// attention via tf32 mma.sync (m16n8k8) — unchanged from R6 (proven).
// =================================================================================
#define KV_STRIDE 68
#define P_STRIDE  72

__global__ __launch_bounds__(128) void k_attn_mma(
    const float* __restrict__ q, const float* __restrict__ kv, float* __restrict__ pre)
{
    __shared__ __align__(16) uint32_t kvs[64 * KV_STRIDE];
    __shared__ __align__(16) uint32_t Pbuf[4 * 16 * P_STRIDE];

    const int bh = blockIdx.y;
    const int b = bh >> 3, h = bh & 7;
    const int warp = threadIdx.x >> 5;
    const int lane = threadIdx.x & 31;
    const int gid = lane >> 2, tig = lane & 3;
    const int n0 = blockIdx.x * 64;

    {
        float* stage = (float*)Pbuf;   // [64][33]
        #pragma unroll
        for (int i = 0; i < 4; i++) {
            int idx = threadIdx.x + 128 * i;
            int r = idx >> 3, v4 = (idx & 7) * 4;
            float4 t = *(const float4*)&q[((size_t)b * 4096 + n0 + r) * 256 + h * 32 + v4];
            stage[r * 33 + v4 + 0] = t.x;
            stage[r * 33 + v4 + 1] = t.y;
            stage[r * 33 + v4 + 2] = t.z;
            stage[r * 33 + v4 + 3] = t.w;
        }
    }
    __syncthreads();

    uint32_t qA[4][4];
    {
        const float* stage = (const float*)Pbuf;
        int r0 = warp * 16 + gid;
        #pragma unroll
        for (int ks = 0; ks < 4; ks++) {
            int c = ks * 8 + tig;
            qA[ks][0] = f2tf(stage[r0 * 33 + c]);
            qA[ks][1] = f2tf(stage[(r0 + 8) * 33 + c]);
            qA[ks][2] = f2tf(stage[r0 * 33 + c + 4]);
            qA[ks][3] = f2tf(stage[(r0 + 8) * 33 + c + 4]);
        }
    }

    float O[4][4];
    #pragma unroll
    for (int i = 0; i < 4; i++)
        #pragma unroll
        for (int j = 0; j < 4; j++) O[i][j] = 0.0f;
    float l_lo = 0.0f, l_hi = 0.0f;

    const float* kvb = kv + (size_t)b * 1024 * 512 + h * 64;
    const float SCL = 0.17677669529663687f;
    uint32_t* Pw = Pbuf + warp * 16 * P_STRIDE;

    for (int mc = 0; mc < 1024; mc += 64) {
        __syncthreads();
        #pragma unroll
        for (int ii = 0; ii < 8; ii++) {
            int idx = threadIdx.x + 128 * ii;
            int r = idx >> 4;
            int jc = (idx & 15) * 4;
            float4 t = *(const float4*)&kvb[(size_t)(mc + r) * 512 + jc];
            uint4 u;
            u.x = f2tf(t.x); u.y = f2tf(t.y); u.z = f2tf(t.z); u.w = f2tf(t.w);
            *(uint4*)&kvs[r * KV_STRIDE + jc] = u;
        }
        __syncthreads();

        float S[8][4];
        #pragma unroll
        for (int nt = 0; nt < 8; nt++) {
            S[nt][0] = S[nt][1] = S[nt][2] = S[nt][3] = 0.0f;
            #pragma unroll
            for (int ks = 0; ks < 4; ks++) {
                const uint32_t* krow = &kvs[(nt * 8 + gid) * KV_STRIDE + ks * 8 + tig];
                mma_tf32(S[nt], qA[ks], krow[0], krow[4]);
            }
        }

        #pragma unroll
        for (int nt = 0; nt < 8; nt++) {
            float p0 = __expf(S[nt][0] * SCL);
            float p1 = __expf(S[nt][1] * SCL);
            float p2 = __expf(S[nt][2] * SCL);
            float p3 = __expf(S[nt][3] * SCL);
            l_lo += p0 + p1;
            l_hi += p2 + p3;
            int c = nt * 8 + 2 * tig;
            Pw[gid * P_STRIDE + c]           = f2tf(p0);
            Pw[gid * P_STRIDE + c + 1]       = f2tf(p1);
            Pw[(gid + 8) * P_STRIDE + c]     = f2tf(p2);
            Pw[(gid + 8) * P_STRIDE + c + 1] = f2tf(p3);
        }
        __syncwarp();

        #pragma unroll
        for (int ks = 0; ks < 8; ks++) {
            uint32_t pA[4];
            int c = ks * 8 + tig;
            pA[0] = Pw[gid * P_STRIDE + c];
            pA[1] = Pw[(gid + 8) * P_STRIDE + c];
            pA[2] = Pw[gid * P_STRIDE + c + 4];
            pA[3] = Pw[(gid + 8) * P_STRIDE + c + 4];
            #pragma unroll
            for (int nt = 0; nt < 4; nt++) {
                uint32_t b0 = kvs[(ks * 8 + tig) * KV_STRIDE + 32 + nt * 8 + gid];
                uint32_t b1 = kvs[(ks * 8 + tig + 4) * KV_STRIDE + 32 + nt * 8 + gid];
                mma_tf32(O[nt], pA, b0, b1);
            }
        }
        __syncwarp();
    }

    l_lo += __shfl_xor_sync(0xFFFFFFFF, l_lo, 1);
    l_lo += __shfl_xor_sync(0xFFFFFFFF, l_lo, 2);
    l_hi += __shfl_xor_sync(0xFFFFFFFF, l_hi, 1);
    l_hi += __shfl_xor_sync(0xFFFFFFFF, l_hi, 2);
    float inv_lo = 1.0f / l_lo;
    float inv_hi = 1.0f / l_hi;

    const int rlo = n0 + warp * 16 + gid;
    const int rhi = rlo + 8;
    #pragma unroll
    for (int nt = 0; nt < 4; nt++) {
        int c = h * 32 + nt * 8 + 2 * tig;
        float2 lo = make_float2(O[nt][0] * inv_lo, O[nt][1] * inv_lo);
        float2 hi = make_float2(O[nt][2] * inv_hi, O[nt][3] * inv_hi);
        *(float2*)&pre[((size_t)b * 4096 + rlo) * 256 + c] = lo;
        *(float2*)&pre[((size_t)b * 4096 + rhi) * 256 + c] = hi;
    }
}

// =================================================================================
// depthwise 7x7 conv (pad 3), reads planar v copy (coalesced), -> g_vpe[b][m][c]
// =================================================================================
__global__ __launch_bounds__(256) void k_dwconv(
    const float* __restrict__ vt, const float* __restrict__ Wpe,
    const float* __restrict__ pe_scale, const float* __restrict__ pe_bias,
    float* __restrict__ vpe)
{
    __shared__ float plane[1024];
    __shared__ float wsm[49];
    const int c = blockIdx.x;
    const int b = blockIdx.y;
    const int tid = threadIdx.x;

    *(float4*)&plane[tid * 4] = *(const float4*)&vt[((size_t)b * 256 + c) * 1024 + tid * 4];
    if (tid < 49) wsm[tid] = Wpe[c * 49 + tid];
    __syncthreads();

    const float sc = pe_scale[c], bi = pe_bias[c];
    #pragma unroll
    for (int i = 0; i < 4; i++) {
        int m = tid + 256 * i;
        int y = m >> 5, x = m & 31;
        float s = 0.0f;
        #pragma unroll
        for (int ky = 0; ky < 7; ky++) {
            int iy = y + ky - 3;
            if ((unsigned)iy < 32u) {
                #pragma unroll
                for (int kx = 0; kx < 7; kx++) {
                    int ix = x + kx - 3;
                    if ((unsigned)ix < 32u) s += plane[iy * 32 + ix] * wsm[ky * 7 + kx];
                }
            }
        }
        vpe[((size_t)b * 1024 + m) * 256 + c] = s * sc + bi;
    }
}

// =================================================================================
// bilinear x2 upsample + add into pre
// =================================================================================
__global__ __launch_bounds__(256) void k_upsample_add(
    const float* __restrict__ vpe, float* __restrict__ pre)
{
    const int y = blockIdx.x;
    const int b = blockIdx.y;
    const int c = threadIdx.x;

    float ys = y * 0.5f - 0.25f;
    int y0 = (int)floorf(ys);
    float wy = ys - (float)y0;
    int y0c = max(y0, 0), y1c = min(y0 + 1, 31);

    const float* vb = vpe + (size_t)b * 1024 * 256;

    for (int x = 0; x < 64; x++) {
        float xs = x * 0.5f - 0.25f;
        int x0 = (int)floorf(xs);
        float wx = xs - (float)x0;
        int x0c = max(x0, 0), x1c = min(x0 + 1, 31);

        float v00 = vb[(y0c * 32 + x0c) * 256 + c];
        float v01 = vb[(y0c * 32 + x1c) * 256 + c];
        float v10 = vb[(y1c * 32 + x0c) * 256 + c];
        float v11 = vb[(y1c * 32 + x1c) * 256 + c];
        float val = (1.f - wy) * ((1.f - wx) * v00 + wx * v01)
                  +        wy  * ((1.f - wx) * v10 + wx * v11);

        size_t o = ((size_t)b * 4096 + y * 64 + x) * 256 + c;
        pre[o] += val;
    }
}

// =================================================================================
// launch
// =================================================================================
extern "C" void kernel_launch(void* const* d_in, const int* in_sizes, int n_in,
                              void* d_out, int out_size)
{
    (void)in_sizes; (void)n_in; (void)out_size;
    const float* x          = (const float*)d_in[0];
    const float* upper_feat = (const float*)d_in[1];
    const float* Wq         = (const float*)d_in[2];
    const float* q_scale    = (const float*)d_in[3];
    const float* q_bias     = (const float*)d_in[4];
    const float* Wkv        = (const float*)d_in[5];
    const float* kv_scale   = (const float*)d_in[6];
    const float* kv_bias    = (const float*)d_in[7];
    const float* Wpe        = (const float*)d_in[8];
    const float* pe_scale   = (const float*)d_in[9];
    const float* pe_bias    = (const float*)d_in[10];
    const float* Wproj      = (const float*)d_in[11];
    const float* proj_scale = (const float*)d_in[12];
    const float* proj_bias  = (const float*)d_in[13];
    float* out = (float*)d_out;

    float *pq, *pkv, *pvt, *pvpe, *ppre;
    cudaGetSymbolAddress((void**)&pq,   g_q);
    cudaGetSymbolAddress((void**)&pkv,  g_kv);
    cudaGetSymbolAddress((void**)&pvt,  g_vt);
    cudaGetSymbolAddress((void**)&pvpe, g_vpe);
    cudaGetSymbolAddress((void**)&ppre, g_pre);

    // q = conv1x1(x; Wq) -> g_q [b][n][256]
    k_conv_tf32_nmajor<<<dim3(4, 32, 4), 256>>>(x, Wq, q_scale, q_bias, pq, nullptr, 256, 4096, 256);
    // kv = conv1x1(upper; Wkv) -> g_kv [b][m][512] (+ planar v copy -> g_vt)
    k_conv_tf32_nmajor<<<dim3(8, 8, 4), 256>>>(upper_feat, Wkv, kv_scale, kv_bias, pkv, pvt, 256, 1024, 512);
    // attention -> g_pre
    k_attn_mma<<<dim3(64, 32), 128>>>(pq, pkv, ppre);
    // depthwise 7x7 on v (planar, coalesced) -> g_vpe
    k_dwconv<<<dim3(256, 4), 256>>>(pvt, Wpe, pe_scale, pe_bias, pvpe);
    // pre += upsample(vpe)
    k_upsample_add<<<dim3(64, 4), 256>>>(pvpe, ppre);
    // out = conv1x1(pre; Wproj) -> planar
    k_conv_tf32_proj<<<dim3(2, 64, 4), 256>>>(ppre, Wproj, proj_scale, proj_bias, out, 256, 4096, 256);
}

// round 8
// speedup vs baseline: 2.8894x; 1.1407x over previous
#include <cuda_runtime.h>
#include <math.h>
#include <stdint.h>

// ---------------- scratch (static device globals; no allocation) ----------------
__device__ float g_q  [(size_t)4 * 4096 * 256];   // [b][n][oc]   tf32 bits
__device__ float g_kv [(size_t)4 * 1024 * 512];   // [b][m][oc]   tf32 bits
__device__ float g_vt [(size_t)4 * 256 * 1024];   // [b][c][m]    fp32 planar v copy
__device__ float g_vpe[(size_t)4 * 1024 * 256];   // [b][m][c]
__device__ float g_pre[(size_t)4 * 4096 * 256];   // [b][n][c]

// ---------------- tf32 helpers ----------------
__device__ __forceinline__ uint32_t f2tf(float f) {
    uint32_t r; asm("cvt.rna.tf32.f32 %0, %1;" : "=r"(r) : "f"(f)); return r;
}
__device__ __forceinline__ void mma_tf32(float c[4], const uint32_t a[4],
                                         uint32_t b0, uint32_t b1) {
    asm("mma.sync.aligned.m16n8k8.row.col.f32.tf32.tf32.f32 "
        "{%0,%1,%2,%3}, {%4,%5,%6,%7}, {%8,%9}, {%0,%1,%2,%3};"
        : "+f"(c[0]), "+f"(c[1]), "+f"(c[2]), "+f"(c[3])
        : "r"(a[0]), "r"(a[1]), "r"(a[2]), "r"(a[3]), "r"(b0), "r"(b1));
}

// =================================================================================
// tf32 conv1x1, input planar [C][Nsp], output n-major [Nsp][O]
// tile 128n x 64o. tf32_out: store tf32 bit pattern (consumed by attention).
// vt (optional): fp32 planar scatter of v half-channels (kv conv only).
// =================================================================================
__global__ __launch_bounds__(256) void k_conv_tf32_nmajor(
    const float* __restrict__ X, const float* __restrict__ W,
    const float* __restrict__ scale, const float* __restrict__ bias,
    float* __restrict__ out, float* __restrict__ vt, int C, int Nsp, int O)
{
    __shared__ __align__(16) uint32_t As[32 * 136];
    __shared__ __align__(16) uint32_t Ws[64 * 36];
    const int b  = blockIdx.z;
    const int n0 = blockIdx.y * 128;
    const int o0 = blockIdx.x * 64;
    const int tid = threadIdx.x;
    const int warp = tid >> 5, lane = tid & 31;
    const int gid = lane >> 2, tig = lane & 3;
    const int wm = warp * 16;

    const float* Xb = X + (size_t)b * C * Nsp;
    float Cacc[8][4];
    #pragma unroll
    for (int i = 0; i < 8; i++)
        #pragma unroll
        for (int j = 0; j < 4; j++) Cacc[i][j] = 0.0f;

    for (int c0 = 0; c0 < C; c0 += 32) {
        __syncthreads();
        #pragma unroll
        for (int i = 0; i < 4; i++) {
            int idx = tid + 256 * i;
            int k = idx >> 5;
            int mq = (idx & 31) * 4;
            float4 t = *(const float4*)&Xb[(size_t)(c0 + k) * Nsp + n0 + mq];
            uint4 u; u.x = f2tf(t.x); u.y = f2tf(t.y); u.z = f2tf(t.z); u.w = f2tf(t.w);
            *(uint4*)&As[k * 136 + mq] = u;
        }
        #pragma unroll
        for (int i = 0; i < 2; i++) {
            int idx = tid + 256 * i;
            int o = idx >> 3;
            int kq = (idx & 7) * 4;
            float4 t = *(const float4*)&W[(size_t)(o0 + o) * C + c0 + kq];
            uint4 u; u.x = f2tf(t.x); u.y = f2tf(t.y); u.z = f2tf(t.z); u.w = f2tf(t.w);
            *(uint4*)&Ws[o * 36 + kq] = u;
        }
        __syncthreads();
        #pragma unroll
        for (int ks = 0; ks < 4; ks++) {
            int kk = ks * 8 + tig;
            uint32_t aF[4];
            aF[0] = As[kk * 136 + wm + gid];
            aF[1] = As[kk * 136 + wm + gid + 8];
            aF[2] = As[(kk + 4) * 136 + wm + gid];
            aF[3] = As[(kk + 4) * 136 + wm + gid + 8];
            #pragma unroll
            for (int nt = 0; nt < 8; nt++) {
                uint32_t b0 = Ws[(nt * 8 + gid) * 36 + kk];
                uint32_t b1 = Ws[(nt * 8 + gid) * 36 + kk + 4];
                mma_tf32(Cacc[nt], aF, b0, b1);
            }
        }
    }

    const int nlo = n0 + wm + gid, nhi = nlo + 8;
    #pragma unroll
    for (int nt = 0; nt < 8; nt++) {
        int o = o0 + nt * 8 + 2 * tig;
        float2 sc = *(const float2*)&scale[o];
        float2 bi = *(const float2*)&bias[o];
        float2 lo, hi;
        lo.x = Cacc[nt][0] * sc.x + bi.x;
        lo.y = Cacc[nt][1] * sc.y + bi.y;
        hi.x = Cacc[nt][2] * sc.x + bi.x;
        hi.y = Cacc[nt][3] * sc.y + bi.y;
        if (vt != nullptr && (o & 32)) {
            int vc = (o >> 6) * 32 + (o & 31);
            vt[((size_t)b * 256 + vc)     * Nsp + nlo] = lo.x;
            vt[((size_t)b * 256 + vc + 1) * Nsp + nlo] = lo.y;
            vt[((size_t)b * 256 + vc)     * Nsp + nhi] = hi.x;
            vt[((size_t)b * 256 + vc + 1) * Nsp + nhi] = hi.y;
        }
        // store tf32 bit pattern (attention consumes these buffers as tf32)
        lo.x = __uint_as_float(f2tf(lo.x));
        lo.y = __uint_as_float(f2tf(lo.y));
        hi.x = __uint_as_float(f2tf(hi.x));
        hi.y = __uint_as_float(f2tf(hi.y));
        *(float2*)&out[((size_t)b * Nsp + nlo) * O + o] = lo;
        *(float2*)&out[((size_t)b * Nsp + nhi) * O + o] = hi;
    }
}

// =================================================================================
// tf32 conv1x1 projection: input row-major [Nsp][C], output planar [O][Nsp]
// =================================================================================
__global__ __launch_bounds__(256) void k_conv_tf32_proj(
    const float* __restrict__ Ain, const float* __restrict__ W,
    const float* __restrict__ scale, const float* __restrict__ bias,
    float* __restrict__ out, int C, int Nsp, int O)
{
    __shared__ __align__(16) uint32_t Wa[128 * 36];
    __shared__ __align__(16) uint32_t Ab[64 * 36];
    const int b  = blockIdx.z;
    const int o0 = blockIdx.x * 128;
    const int n0 = blockIdx.y * 64;
    const int tid = threadIdx.x;
    const int warp = tid >> 5, lane = tid & 31;
    const int gid = lane >> 2, tig = lane & 3;
    const int wm = warp * 16;

    const float* Ainb = Ain + (size_t)b * Nsp * C;
    float Cacc[8][4];
    #pragma unroll
    for (int i = 0; i < 8; i++)
        #pragma unroll
        for (int j = 0; j < 4; j++) Cacc[i][j] = 0.0f;

    for (int c0 = 0; c0 < C; c0 += 32) {
        __syncthreads();
        #pragma unroll
        for (int i = 0; i < 4; i++) {
            int idx = tid + 256 * i;
            int o = idx >> 3;
            int kq = (idx & 7) * 4;
            float4 t = *(const float4*)&W[(size_t)(o0 + o) * C + c0 + kq];
            uint4 u; u.x = f2tf(t.x); u.y = f2tf(t.y); u.z = f2tf(t.z); u.w = f2tf(t.w);
            *(uint4*)&Wa[o * 36 + kq] = u;
        }
        #pragma unroll
        for (int i = 0; i < 2; i++) {
            int idx = tid + 256 * i;
            int n = idx >> 3;
            int kq = (idx & 7) * 4;
            float4 t = *(const float4*)&Ainb[(size_t)(n0 + n) * C + c0 + kq];
            uint4 u; u.x = f2tf(t.x); u.y = f2tf(t.y); u.z = f2tf(t.z); u.w = f2tf(t.w);
            *(uint4*)&Ab[n * 36 + kq] = u;
        }
        __syncthreads();
        #pragma unroll
        for (int ks = 0; ks < 4; ks++) {
            int kk = ks * 8 + tig;
            uint32_t aF[4];
            aF[0] = Wa[(wm + gid) * 36 + kk];
            aF[1] = Wa[(wm + gid + 8) * 36 + kk];
            aF[2] = Wa[(wm + gid) * 36 + kk + 4];
            aF[3] = Wa[(wm + gid + 8) * 36 + kk + 4];
            #pragma unroll
            for (int nt = 0; nt < 8; nt++) {
                uint32_t b0 = Ab[(nt * 8 + gid) * 36 + kk];
                uint32_t b1 = Ab[(nt * 8 + gid) * 36 + kk + 4];
                mma_tf32(Cacc[nt], aF, b0, b1);
            }
        }
    }

    const int olo = o0 + wm + gid, ohi = olo + 8;
    const float sclo = scale[olo], bilo = bias[olo];
    const float schi = scale[ohi], bihi = bias[ohi];
    #pragma unroll
    for (int nt = 0; nt < 8; nt++) {
        int n = n0 + nt * 8 + 2 * tig;
        float2 lo, hi;
        lo.x = Cacc[nt][0] * sclo + bilo;
        lo.y = Cacc[nt][1] * sclo + bilo;
        hi.x = Cacc[nt][2] * schi + bihi;
        hi.y = Cacc[nt][3] * schi + bihi;
        *(float2*)&out[((size_t)b * O + olo) * Nsp + n] = lo;
        *(float2*)&out[((size_t)b * O + ohi) * Nsp + n] = hi;
    }
}

// =================================================================================
// attention v2: 256 threads, 128 q rows/block, cp.async double-buffered kv,
// P exchanged C-frag -> A-frag via quad shuffles (no smem round trip).
// q/kv buffers already hold tf32 bit patterns.
// =================================================================================
__global__ __launch_bounds__(256) void k_attn_mma2(
    const uint32_t* __restrict__ q, const uint32_t* __restrict__ kv,
    float* __restrict__ pre)
{
    __shared__ __align__(16) uint32_t kvs[2][64 * 68];

    const int bh = blockIdx.y;
    const int b = bh >> 3, h = bh & 7;
    const int tid = threadIdx.x;
    const int warp = tid >> 5, lane = tid & 31;
    const int gid = lane >> 2, tig = lane & 3;
    const int n0 = blockIdx.x * 128;

    // ---- stage q tile [128][32] into kvs region (stride 33), build A-frags ----
    {
        uint32_t* stage = &kvs[0][0];
        #pragma unroll
        for (int i = 0; i < 4; i++) {
            int idx = tid + 256 * i;               // 0..1023
            int r = idx >> 3, v4 = (idx & 7) * 4;
            uint4 t = *(const uint4*)&q[((size_t)b * 4096 + n0 + r) * 256 + h * 32 + v4];
            stage[r * 33 + v4 + 0] = t.x;
            stage[r * 33 + v4 + 1] = t.y;
            stage[r * 33 + v4 + 2] = t.z;
            stage[r * 33 + v4 + 3] = t.w;
        }
    }
    __syncthreads();

    uint32_t qA[4][4];
    {
        const uint32_t* stage = &kvs[0][0];
        int r0 = warp * 16 + gid;
        #pragma unroll
        for (int ks = 0; ks < 4; ks++) {
            int c = ks * 8 + tig;
            qA[ks][0] = stage[r0 * 33 + c];
            qA[ks][1] = stage[(r0 + 8) * 33 + c];
            qA[ks][2] = stage[r0 * 33 + c + 4];
            qA[ks][3] = stage[(r0 + 8) * 33 + c + 4];
        }
    }
    __syncthreads();

    const uint32_t* kvb = kv + (size_t)b * 1024 * 512 + h * 64;

    // prefetch chunk 0
    #pragma unroll
    for (int ii = 0; ii < 4; ii++) {
        int idx = tid + 256 * ii;
        int r = idx >> 4, jc = (idx & 15) * 4;
        uint32_t dst = (uint32_t)__cvta_generic_to_shared(&kvs[0][r * 68 + jc]);
        const uint32_t* src = &kvb[(size_t)r * 512 + jc];
        asm volatile("cp.async.cg.shared.global [%0], [%1], 16;" :: "r"(dst), "l"(src));
    }
    asm volatile("cp.async.commit_group;" ::: "memory");

    float O[4][4];
    #pragma unroll
    for (int i = 0; i < 4; i++)
        #pragma unroll
        for (int j = 0; j < 4; j++) O[i][j] = 0.0f;
    float l_lo = 0.0f, l_hi = 0.0f;
    const float SCL = 0.17677669529663687f;   // 1/sqrt(32)

    for (int ci = 0; ci < 16; ci++) {
        const int cur = ci & 1;
        if (ci < 15) {
            #pragma unroll
            for (int ii = 0; ii < 4; ii++) {
                int idx = tid + 256 * ii;
                int r = idx >> 4, jc = (idx & 15) * 4;
                uint32_t dst = (uint32_t)__cvta_generic_to_shared(&kvs[cur ^ 1][r * 68 + jc]);
                const uint32_t* src = &kvb[(size_t)((ci + 1) * 64 + r) * 512 + jc];
                asm volatile("cp.async.cg.shared.global [%0], [%1], 16;" :: "r"(dst), "l"(src));
            }
            asm volatile("cp.async.commit_group;" ::: "memory");
            asm volatile("cp.async.wait_group 1;" ::: "memory");
        } else {
            asm volatile("cp.async.wait_group 0;" ::: "memory");
        }
        __syncthreads();

        const uint32_t* kc = &kvs[cur][0];
        #pragma unroll
        for (int nt = 0; nt < 8; nt++) {
            // ---- QK for this 8-col kv block ----
            float S[4] = {0.f, 0.f, 0.f, 0.f};
            #pragma unroll
            for (int ks = 0; ks < 4; ks++) {
                const uint32_t* krow = &kc[(nt * 8 + gid) * 68 + ks * 8 + tig];
                mma_tf32(S, qA[ks], krow[0], krow[4]);
            }
            // ---- exp + row-sum partials ----
            float p0 = __expf(S[0] * SCL);
            float p1 = __expf(S[1] * SCL);
            float p2 = __expf(S[2] * SCL);
            float p3 = __expf(S[3] * SCL);
            l_lo += p0 + p1;
            l_hi += p2 + p3;
            // ---- C-frag -> A-frag exchange via quad shuffles ----
            int s1 = (lane & ~3) | (tig >> 1);
            int s2 = s1 + 2;
            float a0q = __shfl_sync(0xFFFFFFFFu, p0, s1);
            float a1q = __shfl_sync(0xFFFFFFFFu, p1, s1);
            float a2q = __shfl_sync(0xFFFFFFFFu, p2, s1);
            float a3q = __shfl_sync(0xFFFFFFFFu, p3, s1);
            float a0r = __shfl_sync(0xFFFFFFFFu, p0, s2);
            float a1r = __shfl_sync(0xFFFFFFFFu, p1, s2);
            float a2r = __shfl_sync(0xFFFFFFFFu, p2, s2);
            float a3r = __shfl_sync(0xFFFFFFFFu, p3, s2);
            bool e = (tig & 1);
            uint32_t pA[4];
            pA[0] = f2tf(e ? a1q : a0q);   // (gid,   tig)
            pA[1] = f2tf(e ? a3q : a2q);   // (gid+8, tig)
            pA[2] = f2tf(e ? a1r : a0r);   // (gid,   tig+4)
            pA[3] = f2tf(e ? a3r : a2r);   // (gid+8, tig+4)
            // ---- AV for this kv block ----
            #pragma unroll
            for (int mt = 0; mt < 4; mt++) {
                uint32_t b0 = kc[(nt * 8 + tig) * 68 + 32 + mt * 8 + gid];
                uint32_t b1 = kc[(nt * 8 + tig + 4) * 68 + 32 + mt * 8 + gid];
                mma_tf32(O[mt], pA, b0, b1);
            }
        }
        __syncthreads();
    }

    // ---- reduce l across the tig quad, normalize, write ----
    l_lo += __shfl_xor_sync(0xFFFFFFFF, l_lo, 1);
    l_lo += __shfl_xor_sync(0xFFFFFFFF, l_lo, 2);
    l_hi += __shfl_xor_sync(0xFFFFFFFF, l_hi, 1);
    l_hi += __shfl_xor_sync(0xFFFFFFFF, l_hi, 2);
    float inv_lo = 1.0f / l_lo;
    float inv_hi = 1.0f / l_hi;

    const int rlo = n0 + warp * 16 + gid;
    const int rhi = rlo + 8;
    #pragma unroll
    for (int mt = 0; mt < 4; mt++) {
        int c = h * 32 + mt * 8 + 2 * tig;
        float2 lo = make_float2(O[mt][0] * inv_lo, O[mt][1] * inv_lo);
        float2 hi = make_float2(O[mt][2] * inv_hi, O[mt][3] * inv_hi);
        *(float2*)&pre[((size_t)b * 4096 + rlo) * 256 + c] = lo;
        *(float2*)&pre[((size_t)b * 4096 + rhi) * 256 + c] = hi;
    }
}

// =================================================================================
// depthwise 7x7 conv (pad 3), reads planar v copy (coalesced) -> g_vpe[b][m][c]
// =================================================================================
__global__ __launch_bounds__(256) void k_dwconv(
    const float* __restrict__ vt, const float* __restrict__ Wpe,
    const float* __restrict__ pe_scale, const float* __restrict__ pe_bias,
    float* __restrict__ vpe)
{
    __shared__ float plane[1024];
    __shared__ float wsm[49];
    const int c = blockIdx.x;
    const int b = blockIdx.y;
    const int tid = threadIdx.x;

    *(float4*)&plane[tid * 4] = *(const float4*)&vt[((size_t)b * 256 + c) * 1024 + tid * 4];
    if (tid < 49) wsm[tid] = Wpe[c * 49 + tid];
    __syncthreads();

    const float sc = pe_scale[c], bi = pe_bias[c];
    #pragma unroll
    for (int i = 0; i < 4; i++) {
        int m = tid + 256 * i;
        int y = m >> 5, x = m & 31;
        float s = 0.0f;
        #pragma unroll
        for (int ky = 0; ky < 7; ky++) {
            int iy = y + ky - 3;
            if ((unsigned)iy < 32u) {
                #pragma unroll
                for (int kx = 0; kx < 7; kx++) {
                    int ix = x + kx - 3;
                    if ((unsigned)ix < 32u) s += plane[iy * 32 + ix] * wsm[ky * 7 + kx];
                }
            }
        }
        vpe[((size_t)b * 1024 + m) * 256 + c] = s * sc + bi;
    }
}

// =================================================================================
// bilinear x2 upsample + add into pre
// =================================================================================
__global__ __launch_bounds__(256) void k_upsample_add(
    const float* __restrict__ vpe, float* __restrict__ pre)
{
    const int y = blockIdx.x;
    const int b = blockIdx.y;
    const int c = threadIdx.x;

    float ys = y * 0.5f - 0.25f;
    int y0 = (int)floorf(ys);
    float wy = ys - (float)y0;
    int y0c = max(y0, 0), y1c = min(y0 + 1, 31);

    const float* vb = vpe + (size_t)b * 1024 * 256;

    for (int x = 0; x < 64; x++) {
        float xs = x * 0.5f - 0.25f;
        int x0 = (int)floorf(xs);
        float wx = xs - (float)x0;
        int x0c = max(x0, 0), x1c = min(x0 + 1, 31);

        float v00 = vb[(y0c * 32 + x0c) * 256 + c];
        float v01 = vb[(y0c * 32 + x1c) * 256 + c];
        float v10 = vb[(y1c * 32 + x0c) * 256 + c];
        float v11 = vb[(y1c * 32 + x1c) * 256 + c];
        float val = (1.f - wy) * ((1.f - wx) * v00 + wx * v01)
                  +        wy  * ((1.f - wx) * v10 + wx * v11);

        size_t o = ((size_t)b * 4096 + y * 64 + x) * 256 + c;
        pre[o] += val;
    }
}

// =================================================================================
// launch
// =================================================================================
extern "C" void kernel_launch(void* const* d_in, const int* in_sizes, int n_in,
                              void* d_out, int out_size)
{
    (void)in_sizes; (void)n_in; (void)out_size;
    const float* x          = (const float*)d_in[0];
    const float* upper_feat = (const float*)d_in[1];
    const float* Wq         = (const float*)d_in[2];
    const float* q_scale    = (const float*)d_in[3];
    const float* q_bias     = (const float*)d_in[4];
    const float* Wkv        = (const float*)d_in[5];
    const float* kv_scale   = (const float*)d_in[6];
    const float* kv_bias    = (const float*)d_in[7];
    const float* Wpe        = (const float*)d_in[8];
    const float* pe_scale   = (const float*)d_in[9];
    const float* pe_bias    = (const float*)d_in[10];
    const float* Wproj      = (const float*)d_in[11];
    const float* proj_scale = (const float*)d_in[12];
    const float* proj_bias  = (const float*)d_in[13];
    float* out = (float*)d_out;

    float *pq, *pkv, *pvt, *pvpe, *ppre;
    cudaGetSymbolAddress((void**)&pq,   g_q);
    cudaGetSymbolAddress((void**)&pkv,  g_kv);
    cudaGetSymbolAddress((void**)&pvt,  g_vt);
    cudaGetSymbolAddress((void**)&pvpe, g_vpe);
    cudaGetSymbolAddress((void**)&ppre, g_pre);

    // q = conv1x1(x; Wq) -> g_q (tf32 bits)
    k_conv_tf32_nmajor<<<dim3(4, 32, 4), 256>>>(x, Wq, q_scale, q_bias, pq, nullptr, 256, 4096, 256);
    // kv = conv1x1(upper; Wkv) -> g_kv (tf32 bits) + fp32 planar v -> g_vt
    k_conv_tf32_nmajor<<<dim3(8, 8, 4), 256>>>(upper_feat, Wkv, kv_scale, kv_bias, pkv, pvt, 256, 1024, 512);
    // attention -> g_pre
    k_attn_mma2<<<dim3(32, 32), 256>>>((const uint32_t*)pq, (const uint32_t*)pkv, ppre);
    // depthwise 7x7 on v (planar, coalesced) -> g_vpe
    k_dwconv<<<dim3(256, 4), 256>>>(pvt, Wpe, pe_scale, pe_bias, pvpe);
    // pre += upsample(vpe)
    k_upsample_add<<<dim3(64, 4), 256>>>(pvpe, ppre);
    // out = conv1x1(pre; Wproj) -> planar
    k_conv_tf32_proj<<<dim3(2, 64, 4), 256>>>(ppre, Wproj, proj_scale, proj_bias, out, 256, 4096, 256);
}

// round 9
// speedup vs baseline: 3.1366x; 1.0856x over previous
#include <cuda_runtime.h>
#include <math.h>
#include <stdint.h>

// ---------------- scratch (static device globals; no allocation) ----------------
__device__ float g_q  [(size_t)4 * 4096 * 256];   // [b][n][oc]   tf32 bits
__device__ float g_kv [(size_t)4 * 1024 * 512];   // [b][m][oc]   tf32 bits
__device__ float g_vt [(size_t)4 * 256 * 1024];   // [b][c][m]    fp32 planar v copy
__device__ float g_vpe[(size_t)4 * 1024 * 256];   // [b][m][c]
__device__ float g_pre[(size_t)4 * 4096 * 256];   // [b][n][c]

// ---------------- tf32 helpers ----------------
__device__ __forceinline__ uint32_t f2tf(float f) {
    uint32_t r; asm("cvt.rna.tf32.f32 %0, %1;" : "=r"(r) : "f"(f)); return r;
}
__device__ __forceinline__ void mma_tf32(float c[4], const uint32_t a[4],
                                         uint32_t b0, uint32_t b1) {
    asm("mma.sync.aligned.m16n8k8.row.col.f32.tf32.tf32.f32 "
        "{%0,%1,%2,%3}, {%4,%5,%6,%7}, {%8,%9}, {%0,%1,%2,%3};"
        : "+f"(c[0]), "+f"(c[1]), "+f"(c[2]), "+f"(c[3])
        : "r"(a[0]), "r"(a[1]), "r"(a[2]), "r"(a[3]), "r"(b0), "r"(b1));
}

// smem column swizzle for the attention kv tile (stride 64 words):
// phys_col = j ^ (((r&3)<<3) | (r&4))  -> QK and AV frag loads both conflict-free
#define KVSW(r, j) ((j) ^ ((((r) & 3) << 3) | ((r) & 4)))

// =================================================================================
// tf32 conv1x1, input planar [C][Nsp], output n-major [Nsp][O]
// tile 128n x 64o, software-pipelined global loads (reg prefetch).
// =================================================================================
__global__ __launch_bounds__(256) void k_conv_tf32_nmajor(
    const float* __restrict__ X, const float* __restrict__ W,
    const float* __restrict__ scale, const float* __restrict__ bias,
    float* __restrict__ out, float* __restrict__ vt, int C, int Nsp, int O)
{
    __shared__ __align__(16) uint32_t As[32 * 136];
    __shared__ __align__(16) uint32_t Ws[64 * 36];
    const int b  = blockIdx.z;
    const int n0 = blockIdx.y * 128;
    const int o0 = blockIdx.x * 64;
    const int tid = threadIdx.x;
    const int warp = tid >> 5, lane = tid & 31;
    const int gid = lane >> 2, tig = lane & 3;
    const int wm = warp * 16;

    const float* Xb = X + (size_t)b * C * Nsp;
    float Cacc[8][4];
    #pragma unroll
    for (int i = 0; i < 8; i++)
        #pragma unroll
        for (int j = 0; j < 4; j++) Cacc[i][j] = 0.0f;

    float4 ra[4], rb[2];
    // prefetch c0 = 0
    #pragma unroll
    for (int i = 0; i < 4; i++) {
        int idx = tid + 256 * i;
        int k = idx >> 5, mq = (idx & 31) * 4;
        ra[i] = *(const float4*)&Xb[(size_t)k * Nsp + n0 + mq];
    }
    #pragma unroll
    for (int i = 0; i < 2; i++) {
        int idx = tid + 256 * i;
        int o = idx >> 3, kq = (idx & 7) * 4;
        rb[i] = *(const float4*)&W[(size_t)(o0 + o) * C + kq];
    }

    for (int c0 = 0; c0 < C; c0 += 32) {
        // stage current chunk (cvt to tf32)
        #pragma unroll
        for (int i = 0; i < 4; i++) {
            int idx = tid + 256 * i;
            int k = idx >> 5, mq = (idx & 31) * 4;
            uint4 u; u.x = f2tf(ra[i].x); u.y = f2tf(ra[i].y);
                     u.z = f2tf(ra[i].z); u.w = f2tf(ra[i].w);
            *(uint4*)&As[k * 136 + mq] = u;
        }
        #pragma unroll
        for (int i = 0; i < 2; i++) {
            int idx = tid + 256 * i;
            int o = idx >> 3, kq = (idx & 7) * 4;
            uint4 u; u.x = f2tf(rb[i].x); u.y = f2tf(rb[i].y);
                     u.z = f2tf(rb[i].z); u.w = f2tf(rb[i].w);
            *(uint4*)&Ws[o * 36 + kq] = u;
        }
        __syncthreads();
        // prefetch next chunk (latency hides under MMA)
        if (c0 + 32 < C) {
            #pragma unroll
            for (int i = 0; i < 4; i++) {
                int idx = tid + 256 * i;
                int k = idx >> 5, mq = (idx & 31) * 4;
                ra[i] = *(const float4*)&Xb[(size_t)(c0 + 32 + k) * Nsp + n0 + mq];
            }
            #pragma unroll
            for (int i = 0; i < 2; i++) {
                int idx = tid + 256 * i;
                int o = idx >> 3, kq = (idx & 7) * 4;
                rb[i] = *(const float4*)&W[(size_t)(o0 + o) * C + c0 + 32 + kq];
            }
        }
        #pragma unroll
        for (int ks = 0; ks < 4; ks++) {
            int kk = ks * 8 + tig;
            uint32_t aF[4];
            aF[0] = As[kk * 136 + wm + gid];
            aF[1] = As[kk * 136 + wm + gid + 8];
            aF[2] = As[(kk + 4) * 136 + wm + gid];
            aF[3] = As[(kk + 4) * 136 + wm + gid + 8];
            #pragma unroll
            for (int nt = 0; nt < 8; nt++) {
                uint32_t b0 = Ws[(nt * 8 + gid) * 36 + kk];
                uint32_t b1 = Ws[(nt * 8 + gid) * 36 + kk + 4];
                mma_tf32(Cacc[nt], aF, b0, b1);
            }
        }
        __syncthreads();
    }

    const int nlo = n0 + wm + gid, nhi = nlo + 8;
    #pragma unroll
    for (int nt = 0; nt < 8; nt++) {
        int o = o0 + nt * 8 + 2 * tig;
        float2 sc = *(const float2*)&scale[o];
        float2 bi = *(const float2*)&bias[o];
        float2 lo, hi;
        lo.x = Cacc[nt][0] * sc.x + bi.x;
        lo.y = Cacc[nt][1] * sc.y + bi.y;
        hi.x = Cacc[nt][2] * sc.x + bi.x;
        hi.y = Cacc[nt][3] * sc.y + bi.y;
        if (vt != nullptr && (o & 32)) {
            int vc = (o >> 6) * 32 + (o & 31);
            vt[((size_t)b * 256 + vc)     * Nsp + nlo] = lo.x;
            vt[((size_t)b * 256 + vc + 1) * Nsp + nlo] = lo.y;
            vt[((size_t)b * 256 + vc)     * Nsp + nhi] = hi.x;
            vt[((size_t)b * 256 + vc + 1) * Nsp + nhi] = hi.y;
        }
        // store tf32 bit pattern (attention consumes these buffers as tf32)
        lo.x = __uint_as_float(f2tf(lo.x));
        lo.y = __uint_as_float(f2tf(lo.y));
        hi.x = __uint_as_float(f2tf(hi.x));
        hi.y = __uint_as_float(f2tf(hi.y));
        *(float2*)&out[((size_t)b * Nsp + nlo) * O + o] = lo;
        *(float2*)&out[((size_t)b * Nsp + nhi) * O + o] = hi;
    }
}

// =================================================================================
// tf32 conv1x1 projection: input row-major [Nsp][C], output planar [O][Nsp]
// software-pipelined global loads.
// =================================================================================
__global__ __launch_bounds__(256) void k_conv_tf32_proj(
    const float* __restrict__ Ain, const float* __restrict__ W,
    const float* __restrict__ scale, const float* __restrict__ bias,
    float* __restrict__ out, int C, int Nsp, int O)
{
    __shared__ __align__(16) uint32_t Wa[128 * 36];
    __shared__ __align__(16) uint32_t Ab[64 * 36];
    const int b  = blockIdx.z;
    const int o0 = blockIdx.x * 128;
    const int n0 = blockIdx.y * 64;
    const int tid = threadIdx.x;
    const int warp = tid >> 5, lane = tid & 31;
    const int gid = lane >> 2, tig = lane & 3;
    const int wm = warp * 16;

    const float* Ainb = Ain + (size_t)b * Nsp * C;
    float Cacc[8][4];
    #pragma unroll
    for (int i = 0; i < 8; i++)
        #pragma unroll
        for (int j = 0; j < 4; j++) Cacc[i][j] = 0.0f;

    float4 ra[4], rb[2];
    #pragma unroll
    for (int i = 0; i < 4; i++) {
        int idx = tid + 256 * i;
        int o = idx >> 3, kq = (idx & 7) * 4;
        ra[i] = *(const float4*)&W[(size_t)(o0 + o) * C + kq];
    }
    #pragma unroll
    for (int i = 0; i < 2; i++) {
        int idx = tid + 256 * i;
        int n = idx >> 3, kq = (idx & 7) * 4;
        rb[i] = *(const float4*)&Ainb[(size_t)(n0 + n) * C + kq];
    }

    for (int c0 = 0; c0 < C; c0 += 32) {
        #pragma unroll
        for (int i = 0; i < 4; i++) {
            int idx = tid + 256 * i;
            int o = idx >> 3, kq = (idx & 7) * 4;
            uint4 u; u.x = f2tf(ra[i].x); u.y = f2tf(ra[i].y);
                     u.z = f2tf(ra[i].z); u.w = f2tf(ra[i].w);
            *(uint4*)&Wa[o * 36 + kq] = u;
        }
        #pragma unroll
        for (int i = 0; i < 2; i++) {
            int idx = tid + 256 * i;
            int n = idx >> 3, kq = (idx & 7) * 4;
            uint4 u; u.x = f2tf(rb[i].x); u.y = f2tf(rb[i].y);
                     u.z = f2tf(rb[i].z); u.w = f2tf(rb[i].w);
            *(uint4*)&Ab[n * 36 + kq] = u;
        }
        __syncthreads();
        if (c0 + 32 < C) {
            #pragma unroll
            for (int i = 0; i < 4; i++) {
                int idx = tid + 256 * i;
                int o = idx >> 3, kq = (idx & 7) * 4;
                ra[i] = *(const float4*)&W[(size_t)(o0 + o) * C + c0 + 32 + kq];
            }
            #pragma unroll
            for (int i = 0; i < 2; i++) {
                int idx = tid + 256 * i;
                int n = idx >> 3, kq = (idx & 7) * 4;
                rb[i] = *(const float4*)&Ainb[(size_t)(n0 + n) * C + c0 + 32 + kq];
            }
        }
        #pragma unroll
        for (int ks = 0; ks < 4; ks++) {
            int kk = ks * 8 + tig;
            uint32_t aF[4];
            aF[0] = Wa[(wm + gid) * 36 + kk];
            aF[1] = Wa[(wm + gid + 8) * 36 + kk];
            aF[2] = Wa[(wm + gid) * 36 + kk + 4];
            aF[3] = Wa[(wm + gid + 8) * 36 + kk + 4];
            #pragma unroll
            for (int nt = 0; nt < 8; nt++) {
                uint32_t b0 = Ab[(nt * 8 + gid) * 36 + kk];
                uint32_t b1 = Ab[(nt * 8 + gid) * 36 + kk + 4];
                mma_tf32(Cacc[nt], aF, b0, b1);
            }
        }
        __syncthreads();
    }

    const int olo = o0 + wm + gid, ohi = olo + 8;
    const float sclo = scale[olo], bilo = bias[olo];
    const float schi = scale[ohi], bihi = bias[ohi];
    #pragma unroll
    for (int nt = 0; nt < 8; nt++) {
        int n = n0 + nt * 8 + 2 * tig;
        float2 lo, hi;
        lo.x = Cacc[nt][0] * sclo + bilo;
        lo.y = Cacc[nt][1] * sclo + bilo;
        hi.x = Cacc[nt][2] * schi + bihi;
        hi.y = Cacc[nt][3] * schi + bihi;
        *(float2*)&out[((size_t)b * O + olo) * Nsp + n] = lo;
        *(float2*)&out[((size_t)b * O + ohi) * Nsp + n] = hi;
    }
}

// =================================================================================
// attention v3: swizzled kv smem (stride 64, conflict-free QK AND AV),
// cp.async double buffer, shuffle P exchange. q/kv hold tf32 bits.
// =================================================================================
__global__ __launch_bounds__(256) void k_attn_mma2(
    const uint32_t* __restrict__ q, const uint32_t* __restrict__ kv,
    float* __restrict__ pre)
{
    __shared__ __align__(16) uint32_t kvs[2][64 * 64];

    const int bh = blockIdx.y;
    const int b = bh >> 3, h = bh & 7;
    const int tid = threadIdx.x;
    const int warp = tid >> 5, lane = tid & 31;
    const int gid = lane >> 2, tig = lane & 3;
    const int n0 = blockIdx.x * 128;

    // ---- stage q tile [128][32] (stride 33, spans both kvs buffers), A-frags ----
    {
        uint32_t* stage = &kvs[0][0];
        #pragma unroll
        for (int i = 0; i < 4; i++) {
            int idx = tid + 256 * i;               // 0..1023
            int r = idx >> 3, v4 = (idx & 7) * 4;
            uint4 t = *(const uint4*)&q[((size_t)b * 4096 + n0 + r) * 256 + h * 32 + v4];
            stage[r * 33 + v4 + 0] = t.x;
            stage[r * 33 + v4 + 1] = t.y;
            stage[r * 33 + v4 + 2] = t.z;
            stage[r * 33 + v4 + 3] = t.w;
        }
    }
    __syncthreads();

    uint32_t qA[4][4];
    {
        const uint32_t* stage = &kvs[0][0];
        int r0 = warp * 16 + gid;
        #pragma unroll
        for (int ks = 0; ks < 4; ks++) {
            int c = ks * 8 + tig;
            qA[ks][0] = stage[r0 * 33 + c];
            qA[ks][1] = stage[(r0 + 8) * 33 + c];
            qA[ks][2] = stage[r0 * 33 + c + 4];
            qA[ks][3] = stage[(r0 + 8) * 33 + c + 4];
        }
    }
    __syncthreads();

    const uint32_t* kvb = kv + (size_t)b * 1024 * 512 + h * 64;

    // prefetch chunk 0 (swizzled destination)
    #pragma unroll
    for (int ii = 0; ii < 4; ii++) {
        int idx = tid + 256 * ii;
        int r = idx >> 4, jc = (idx & 15) * 4;
        int pj = KVSW(r, jc);
        uint32_t dst = (uint32_t)__cvta_generic_to_shared(&kvs[0][r * 64 + pj]);
        const uint32_t* src = &kvb[(size_t)r * 512 + jc];
        asm volatile("cp.async.cg.shared.global [%0], [%1], 16;" :: "r"(dst), "l"(src));
    }
    asm volatile("cp.async.commit_group;" ::: "memory");

    float O[4][4];
    #pragma unroll
    for (int i = 0; i < 4; i++)
        #pragma unroll
        for (int j = 0; j < 4; j++) O[i][j] = 0.0f;
    float l_lo = 0.0f, l_hi = 0.0f;
    const float SCL = 0.17677669529663687f;   // 1/sqrt(32)

    const int fq = ((gid & 3) << 3) | (gid & 4);   // QK swizzle term (row&7 = gid)
    const int ft0 = tig << 3;                      // AV row tig   (row&7 = tig)
    const int ft1 = (tig << 3) | 4;                // AV row tig+4

    for (int ci = 0; ci < 16; ci++) {
        const int cur = ci & 1;
        if (ci < 15) {
            #pragma unroll
            for (int ii = 0; ii < 4; ii++) {
                int idx = tid + 256 * ii;
                int r = idx >> 4, jc = (idx & 15) * 4;
                int pj = KVSW(r, jc);
                uint32_t dst = (uint32_t)__cvta_generic_to_shared(&kvs[cur ^ 1][r * 64 + pj]);
                const uint32_t* src = &kvb[(size_t)((ci + 1) * 64 + r) * 512 + jc];
                asm volatile("cp.async.cg.shared.global [%0], [%1], 16;" :: "r"(dst), "l"(src));
            }
            asm volatile("cp.async.commit_group;" ::: "memory");
            asm volatile("cp.async.wait_group 1;" ::: "memory");
        } else {
            asm volatile("cp.async.wait_group 0;" ::: "memory");
        }
        __syncthreads();

        const uint32_t* kc = &kvs[cur][0];
        #pragma unroll
        for (int nt = 0; nt < 8; nt++) {
            // ---- QK for this 8-col kv block ----
            float S[4] = {0.f, 0.f, 0.f, 0.f};
            #pragma unroll
            for (int ks = 0; ks < 4; ks++) {
                uint32_t b0 = kc[(nt * 8 + gid) * 64 + ((ks * 8 + tig) ^ fq)];
                uint32_t b1 = kc[(nt * 8 + gid) * 64 + ((ks * 8 + tig + 4) ^ fq)];
                mma_tf32(S, qA[ks], b0, b1);
            }
            // ---- exp + row-sum partials ----
            float p0 = __expf(S[0] * SCL);
            float p1 = __expf(S[1] * SCL);
            float p2 = __expf(S[2] * SCL);
            float p3 = __expf(S[3] * SCL);
            l_lo += p0 + p1;
            l_hi += p2 + p3;
            // ---- C-frag -> A-frag exchange via quad shuffles ----
            int s1 = (lane & ~3) | (tig >> 1);
            int s2 = s1 + 2;
            float a0q = __shfl_sync(0xFFFFFFFFu, p0, s1);
            float a1q = __shfl_sync(0xFFFFFFFFu, p1, s1);
            float a2q = __shfl_sync(0xFFFFFFFFu, p2, s1);
            float a3q = __shfl_sync(0xFFFFFFFFu, p3, s1);
            float a0r = __shfl_sync(0xFFFFFFFFu, p0, s2);
            float a1r = __shfl_sync(0xFFFFFFFFu, p1, s2);
            float a2r = __shfl_sync(0xFFFFFFFFu, p2, s2);
            float a3r = __shfl_sync(0xFFFFFFFFu, p3, s2);
            bool e = (tig & 1);
            uint32_t pA[4];
            pA[0] = f2tf(e ? a1q : a0q);
            pA[1] = f2tf(e ? a3q : a2q);
            pA[2] = f2tf(e ? a1r : a0r);
            pA[3] = f2tf(e ? a3r : a2r);
            // ---- AV for this kv block ----
            #pragma unroll
            for (int mt = 0; mt < 4; mt++) {
                uint32_t b0 = kc[(nt * 8 + tig) * 64 + ((32 + mt * 8 + gid) ^ ft0)];
                uint32_t b1 = kc[(nt * 8 + tig + 4) * 64 + ((32 + mt * 8 + gid) ^ ft1)];
                mma_tf32(O[mt], pA, b0, b1);
            }
        }
        __syncthreads();
    }

    // ---- reduce l across the tig quad, normalize, write ----
    l_lo += __shfl_xor_sync(0xFFFFFFFF, l_lo, 1);
    l_lo += __shfl_xor_sync(0xFFFFFFFF, l_lo, 2);
    l_hi += __shfl_xor_sync(0xFFFFFFFF, l_hi, 1);
    l_hi += __shfl_xor_sync(0xFFFFFFFF, l_hi, 2);
    float inv_lo = 1.0f / l_lo;
    float inv_hi = 1.0f / l_hi;

    const int rlo = n0 + warp * 16 + gid;
    const int rhi = rlo + 8;
    #pragma unroll
    for (int mt = 0; mt < 4; mt++) {
        int c = h * 32 + mt * 8 + 2 * tig;
        float2 lo = make_float2(O[mt][0] * inv_lo, O[mt][1] * inv_lo);
        float2 hi = make_float2(O[mt][2] * inv_hi, O[mt][3] * inv_hi);
        *(float2*)&pre[((size_t)b * 4096 + rlo) * 256 + c] = lo;
        *(float2*)&pre[((size_t)b * 4096 + rhi) * 256 + c] = hi;
    }
}

// =================================================================================
// depthwise 7x7 conv (pad 3), reads planar v copy (coalesced) -> g_vpe[b][m][c]
// =================================================================================
__global__ __launch_bounds__(256) void k_dwconv(
    const float* __restrict__ vt, const float* __restrict__ Wpe,
    const float* __restrict__ pe_scale, const float* __restrict__ pe_bias,
    float* __restrict__ vpe)
{
    __shared__ float plane[1024];
    __shared__ float wsm[49];
    const int c = blockIdx.x;
    const int b = blockIdx.y;
    const int tid = threadIdx.x;

    *(float4*)&plane[tid * 4] = *(const float4*)&vt[((size_t)b * 256 + c) * 1024 + tid * 4];
    if (tid < 49) wsm[tid] = Wpe[c * 49 + tid];
    __syncthreads();

    const float sc = pe_scale[c], bi = pe_bias[c];
    #pragma unroll
    for (int i = 0; i < 4; i++) {
        int m = tid + 256 * i;
        int y = m >> 5, x = m & 31;
        float s = 0.0f;
        #pragma unroll
        for (int ky = 0; ky < 7; ky++) {
            int iy = y + ky - 3;
            if ((unsigned)iy < 32u) {
                #pragma unroll
                for (int kx = 0; kx < 7; kx++) {
                    int ix = x + kx - 3;
                    if ((unsigned)ix < 32u) s += plane[iy * 32 + ix] * wsm[ky * 7 + kx];
                }
            }
        }
        vpe[((size_t)b * 1024 + m) * 256 + c] = s * sc + bi;
    }
}

// =================================================================================
// bilinear x2 upsample + add into pre
// =================================================================================
__global__ __launch_bounds__(256) void k_upsample_add(
    const float* __restrict__ vpe, float* __restrict__ pre)
{
    const int y = blockIdx.x;
    const int b = blockIdx.y;
    const int c = threadIdx.x;

    float ys = y * 0.5f - 0.25f;
    int y0 = (int)floorf(ys);
    float wy = ys - (float)y0;
    int y0c = max(y0, 0), y1c = min(y0 + 1, 31);

    const float* vb = vpe + (size_t)b * 1024 * 256;

    for (int x = 0; x < 64; x++) {
        float xs = x * 0.5f - 0.25f;
        int x0 = (int)floorf(xs);
        float wx = xs - (float)x0;
        int x0c = max(x0, 0), x1c = min(x0 + 1, 31);

        float v00 = vb[(y0c * 32 + x0c) * 256 + c];
        float v01 = vb[(y0c * 32 + x1c) * 256 + c];
        float v10 = vb[(y1c * 32 + x0c) * 256 + c];
        float v11 = vb[(y1c * 32 + x1c) * 256 + c];
        float val = (1.f - wy) * ((1.f - wx) * v00 + wx * v01)
                  +        wy  * ((1.f - wx) * v10 + wx * v11);

        size_t o = ((size_t)b * 4096 + y * 64 + x) * 256 + c;
        pre[o] += val;
    }
}

// =================================================================================
// launch — kv-conv + dwconv chain overlapped on a second stream
// =================================================================================
extern "C" void kernel_launch(void* const* d_in, const int* in_sizes, int n_in,
                              void* d_out, int out_size)
{
    (void)in_sizes; (void)n_in; (void)out_size;
    const float* x          = (const float*)d_in[0];
    const float* upper_feat = (const float*)d_in[1];
    const float* Wq         = (const float*)d_in[2];
    const float* q_scale    = (const float*)d_in[3];
    const float* q_bias     = (const float*)d_in[4];
    const float* Wkv        = (const float*)d_in[5];
    const float* kv_scale   = (const float*)d_in[6];
    const float* kv_bias    = (const float*)d_in[7];
    const float* Wpe        = (const float*)d_in[8];
    const float* pe_scale   = (const float*)d_in[9];
    const float* pe_bias    = (const float*)d_in[10];
    const float* Wproj      = (const float*)d_in[11];
    const float* proj_scale = (const float*)d_in[12];
    const float* proj_bias  = (const float*)d_in[13];
    float* out = (float*)d_out;

    float *pq, *pkv, *pvt, *pvpe, *ppre;
    cudaGetSymbolAddress((void**)&pq,   g_q);
    cudaGetSymbolAddress((void**)&pkv,  g_kv);
    cudaGetSymbolAddress((void**)&pvt,  g_vt);
    cudaGetSymbolAddress((void**)&pvpe, g_vpe);
    cudaGetSymbolAddress((void**)&ppre, g_pre);

    static cudaStream_t s2 = nullptr;
    static cudaEvent_t e_fork = nullptr, e_kv = nullptr, e_dw = nullptr;
    if (s2 == nullptr) {
        cudaStreamCreateWithFlags(&s2, cudaStreamNonBlocking);
        cudaEventCreateWithFlags(&e_fork, cudaEventDisableTiming);
        cudaEventCreateWithFlags(&e_kv,   cudaEventDisableTiming);
        cudaEventCreateWithFlags(&e_dw,   cudaEventDisableTiming);
    }

    // fork
    cudaEventRecord(e_fork, 0);
    cudaStreamWaitEvent(s2, e_fork, 0);

    // stream 2: kv conv -> dwconv
    k_conv_tf32_nmajor<<<dim3(8, 8, 4), 256, 0, s2>>>(upper_feat, Wkv, kv_scale, kv_bias, pkv, pvt, 256, 1024, 512);
    cudaEventRecord(e_kv, s2);
    k_dwconv<<<dim3(256, 4), 256, 0, s2>>>(pvt, Wpe, pe_scale, pe_bias, pvpe);
    cudaEventRecord(e_dw, s2);

    // main stream: q conv, then attention (needs kv)
    k_conv_tf32_nmajor<<<dim3(4, 32, 4), 256>>>(x, Wq, q_scale, q_bias, pq, nullptr, 256, 4096, 256);
    cudaStreamWaitEvent(0, e_kv, 0);
    k_attn_mma2<<<dim3(32, 32), 256>>>((const uint32_t*)pq, (const uint32_t*)pkv, ppre);

    // join: upsample needs attention (stream order) + dwconv (event)
    cudaStreamWaitEvent(0, e_dw, 0);
    k_upsample_add<<<dim3(64, 4), 256>>>(pvpe, ppre);
    k_conv_tf32_proj<<<dim3(2, 64, 4), 256>>>(ppre, Wproj, proj_scale, proj_bias, out, 256, 4096, 256);
}